// round 1
// baseline (speedup 1.0000x reference)
#include <cuda_runtime.h>
#include <math.h>

// Problem constants
#define BSZ  8
#define CDIM 4096
#define TDIM 512
#define NH   8
#define HDIM 64
#define ODIM 512
#define SCALE_INV (1.0f / 22.62741699796952f)   // 1/sqrt(512)

// ---------------- scratch (static device globals; allocation-free) ----------
// P[b][t][s]       : 8 x 512 x 512
// U[b*h][t][e]     : 64 x 512 x 64   (U = P @ Wk_h^T)
// Z[b][o][h*64+e]  : 8 x 512 x 512   (Z_h = Wo_h @ softmax(S))
// G[b][o][t]       : 8 x 512 x 512   (G = Z @ Wv_flat)
__device__ float g_P[BSZ * TDIM * TDIM];
__device__ float g_U[BSZ * NH * TDIM * HDIM];
__device__ float g_Z[BSZ * TDIM * TDIM];
__device__ float g_G[BSZ * TDIM * TDIM];

// =============================================================================
// K1: P[b][t][s] = sum_c q[b][c][t] * k[b][c][s]
// TN gemm, M=N=512, K=4096, batch=8. 128x128 tile, BK=16, 256 thr, 8x8 micro.
// =============================================================================
__global__ void __launch_bounds__(256) k_pmat(const float* __restrict__ q,
                                              const float* __restrict__ kk_)
{
    const int b  = blockIdx.z;
    const int t0 = blockIdx.y * 128;
    const int s0 = blockIdx.x * 128;

    __shared__ float As[16][132];   // [c][t]
    __shared__ float Bs[16][132];   // [c][s]

    const float* qb = q   + (size_t)b * CDIM * TDIM;
    const float* kb = kk_ + (size_t)b * CDIM * TDIM;

    const int tid = threadIdx.x;
    const int tx = tid & 15, ty = tid >> 4;

    float acc[8][8];
#pragma unroll
    for (int m = 0; m < 8; m++)
#pragma unroll
        for (int n = 0; n < 8; n++) acc[m][n] = 0.f;

    for (int c0 = 0; c0 < CDIM; c0 += 16) {
#pragma unroll
        for (int i = 0; i < 2; i++) {
            int idx = tid + i * 256;          // 0..511 float4 slots
            int r   = idx >> 5;               // 0..15  (c row)
            int cc  = (idx & 31) * 4;         // 0..124
            *(float4*)&As[r][cc] = *(const float4*)&qb[(size_t)(c0 + r) * TDIM + t0 + cc];
            *(float4*)&Bs[r][cc] = *(const float4*)&kb[(size_t)(c0 + r) * TDIM + s0 + cc];
        }
        __syncthreads();
#pragma unroll
        for (int p = 0; p < 16; p++) {
            float ra[8], rb[8];
            *(float4*)&ra[0] = *(float4*)&As[p][ty * 8];
            *(float4*)&ra[4] = *(float4*)&As[p][ty * 8 + 4];
            *(float4*)&rb[0] = *(float4*)&Bs[p][tx * 8];
            *(float4*)&rb[4] = *(float4*)&Bs[p][tx * 8 + 4];
#pragma unroll
            for (int m = 0; m < 8; m++)
#pragma unroll
                for (int n = 0; n < 8; n++) acc[m][n] += ra[m] * rb[n];
        }
        __syncthreads();
    }

    float* Pb = g_P + (size_t)b * TDIM * TDIM;
#pragma unroll
    for (int m = 0; m < 8; m++)
#pragma unroll
        for (int n = 0; n < 8; n += 4) {
            float4 v4 = make_float4(acc[m][n], acc[m][n+1], acc[m][n+2], acc[m][n+3]);
            *(float4*)&Pb[(size_t)(t0 + ty * 8 + m) * TDIM + s0 + tx * 8 + n] = v4;
        }
}

// =============================================================================
// K2a: U[b,h][t][e] = sum_s P[b][t][s] * Wk[h][e][s]
// NT gemm, M=512 (t), N=64 (e), K=512 (s). Tile 128x64, BK=16. 8x4 micro.
// =============================================================================
__global__ void __launch_bounds__(256) k_umat(const float* __restrict__ Wk)
{
    const int b  = blockIdx.z;
    const int h  = blockIdx.y;
    const int t0 = blockIdx.x * 128;

    __shared__ float Ps[16][132];   // [s][t]
    __shared__ float Ks[16][68];    // [s][e]

    const float* Pb  = g_P + (size_t)b * TDIM * TDIM;
    const float* Wkh = Wk + (size_t)h * HDIM * TDIM;

    const int tid = threadIdx.x;
    const int tx = tid & 15, ty = tid >> 4;

    float acc[8][4];
#pragma unroll
    for (int m = 0; m < 8; m++)
#pragma unroll
        for (int n = 0; n < 4; n++) acc[m][n] = 0.f;

    for (int s0 = 0; s0 < TDIM; s0 += 16) {
        // P tile: 128 t x 16 s (transpose on store)
#pragma unroll
        for (int i = 0; i < 2; i++) {
            int idx = tid + i * 256;      // 0..511
            int tl  = idx >> 2;           // 0..127
            int sq  = (idx & 3) * 4;
            float4 a = *(const float4*)&Pb[(size_t)(t0 + tl) * TDIM + s0 + sq];
            Ps[sq + 0][tl] = a.x; Ps[sq + 1][tl] = a.y;
            Ps[sq + 2][tl] = a.z; Ps[sq + 3][tl] = a.w;
        }
        // Wk tile: 64 e x 16 s (transpose on store)
        {
            int el = tid >> 2;            // 0..63
            int sq = (tid & 3) * 4;
            float4 a = *(const float4*)&Wkh[(size_t)el * TDIM + s0 + sq];
            Ks[sq + 0][el] = a.x; Ks[sq + 1][el] = a.y;
            Ks[sq + 2][el] = a.z; Ks[sq + 3][el] = a.w;
        }
        __syncthreads();
#pragma unroll
        for (int p = 0; p < 16; p++) {
            float ra[8], rb[4];
            *(float4*)&ra[0] = *(float4*)&Ps[p][ty * 8];
            *(float4*)&ra[4] = *(float4*)&Ps[p][ty * 8 + 4];
            *(float4*)&rb[0] = *(float4*)&Ks[p][tx * 4];
#pragma unroll
            for (int m = 0; m < 8; m++)
#pragma unroll
                for (int n = 0; n < 4; n++) acc[m][n] += ra[m] * rb[n];
        }
        __syncthreads();
    }

    float* Ub = g_U + (size_t)(b * NH + h) * TDIM * HDIM;
#pragma unroll
    for (int m = 0; m < 8; m++) {
        float4 v4 = make_float4(acc[m][0], acc[m][1], acc[m][2], acc[m][3]);
        *(float4*)&Ub[(size_t)(t0 + ty * 8 + m) * HDIM + tx * 4] = v4;
    }
}

// =============================================================================
// K2b: per (b,h): S = Wq_h @ U / sqrt(512); W = softmax_rows(S);
//      Z[b][o][h*64+e] = sum_d Wo[o][h*64+d] * W[d][e]
// One block per (b,h), 256 threads.
// =============================================================================
__global__ void __launch_bounds__(256) k_attn_z(const float* __restrict__ Wq,
                                                const float* __restrict__ Wo)
{
    const int bh = blockIdx.x;
    const int b = bh >> 3, h = bh & 7;

    __shared__ float Ws[64][65];
    __shared__ float Us[32][68];
    __shared__ float Wqs[64][33];

    const float* Ub  = g_U + (size_t)bh * TDIM * HDIM;
    const float* Wqh = Wq + (size_t)h * HDIM * TDIM;

    const int tid = threadIdx.x;
    const int tx = tid & 15, ty = tid >> 4;

    float acc[4][4];
#pragma unroll
    for (int m = 0; m < 4; m++)
#pragma unroll
        for (int n = 0; n < 4; n++) acc[m][n] = 0.f;

    for (int t0 = 0; t0 < TDIM; t0 += 32) {
        // U chunk: 32 t x 64 e, direct (e-contig)
#pragma unroll
        for (int i = 0; i < 2; i++) {
            int idx = tid + i * 256;            // 0..511 float4 slots
            int tl  = idx >> 4;                 // 0..31
            int eq  = (idx & 15) * 4;
            *(float4*)&Us[tl][eq] = *(const float4*)&Ub[(size_t)(t0 + tl) * HDIM + eq];
        }
        // Wq chunk: 64 d x 32 t (scatter)
#pragma unroll
        for (int i = 0; i < 2; i++) {
            int idx = tid + i * 256;
            int d   = idx >> 3;                 // 0..63
            int tq  = (idx & 7) * 4;
            float4 a = *(const float4*)&Wqh[(size_t)d * TDIM + t0 + tq];
            Wqs[d][tq + 0] = a.x; Wqs[d][tq + 1] = a.y;
            Wqs[d][tq + 2] = a.z; Wqs[d][tq + 3] = a.w;
        }
        __syncthreads();
#pragma unroll
        for (int tl = 0; tl < 32; tl++) {
            float ra[4], rb[4];
#pragma unroll
            for (int m = 0; m < 4; m++) ra[m] = Wqs[ty * 4 + m][tl];
#pragma unroll
            for (int n = 0; n < 4; n++) rb[n] = Us[tl][tx * 4 + n];
#pragma unroll
            for (int m = 0; m < 4; m++)
#pragma unroll
                for (int n = 0; n < 4; n++) acc[m][n] += ra[m] * rb[n];
        }
        __syncthreads();
    }

#pragma unroll
    for (int m = 0; m < 4; m++)
#pragma unroll
        for (int n = 0; n < 4; n++)
            Ws[ty * 4 + m][tx * 4 + n] = acc[m][n] * SCALE_INV;
    __syncthreads();

    // row softmax (64 rows, one thread each)
    if (tid < 64) {
        float mx = -1e30f;
#pragma unroll 8
        for (int e = 0; e < 64; e++) mx = fmaxf(mx, Ws[tid][e]);
        float sum = 0.f;
#pragma unroll 8
        for (int e = 0; e < 64; e++) { float ex = expf(Ws[tid][e] - mx); Ws[tid][e] = ex; sum += ex; }
        float inv = 1.f / sum;
#pragma unroll 8
        for (int e = 0; e < 64; e++) Ws[tid][e] *= inv;
    }
    __syncthreads();

    // Z_h = Wo_h @ W  -> Z[b][o][h*64+e]
    float* Zb = g_Z + (size_t)b * TDIM * TDIM;
    for (int idx = tid; idx < ODIM * HDIM; idx += 256) {
        int o = idx >> 6, e = idx & 63;
        const float* wo = Wo + (size_t)o * (NH * HDIM) + h * HDIM;
        float s = 0.f;
#pragma unroll 16
        for (int d = 0; d < 64; d++) s += wo[d] * Ws[d][e];
        Zb[(size_t)o * TDIM + h * HDIM + e] = s;
    }
}

// =============================================================================
// K3: G[b][o][t] = sum_j Z[b][o][j] * Wv_flat[j][t]
// NN gemm, M=N=K=512 per batch. 128x128 tile, BK=16.
// =============================================================================
__global__ void __launch_bounds__(256) k_gmat(const float* __restrict__ Wv)
{
    const int b  = blockIdx.z;
    const int o0 = blockIdx.y * 128;
    const int t0 = blockIdx.x * 128;

    __shared__ float As[16][132];   // [j][o]
    __shared__ float Bs[16][132];   // [j][t]

    const float* Zb = g_Z + (size_t)b * TDIM * TDIM;

    const int tid = threadIdx.x;
    const int tx = tid & 15, ty = tid >> 4;

    float acc[8][8];
#pragma unroll
    for (int m = 0; m < 8; m++)
#pragma unroll
        for (int n = 0; n < 8; n++) acc[m][n] = 0.f;

    for (int j0 = 0; j0 < TDIM; j0 += 16) {
#pragma unroll
        for (int i = 0; i < 2; i++) {
            int idx = tid + i * 256;
            // A: Z[o][j] -> transpose
            int ol = idx >> 2;
            int jq = (idx & 3) * 4;
            float4 a = *(const float4*)&Zb[(size_t)(o0 + ol) * TDIM + j0 + jq];
            As[jq + 0][ol] = a.x; As[jq + 1][ol] = a.y;
            As[jq + 2][ol] = a.z; As[jq + 3][ol] = a.w;
            // B: Wv_flat[j][t] -> direct
            int r  = idx >> 5;
            int cc = (idx & 31) * 4;
            *(float4*)&Bs[r][cc] = *(const float4*)&Wv[(size_t)(j0 + r) * TDIM + t0 + cc];
        }
        __syncthreads();
#pragma unroll
        for (int p = 0; p < 16; p++) {
            float ra[8], rb[8];
            *(float4*)&ra[0] = *(float4*)&As[p][ty * 8];
            *(float4*)&ra[4] = *(float4*)&As[p][ty * 8 + 4];
            *(float4*)&rb[0] = *(float4*)&Bs[p][tx * 8];
            *(float4*)&rb[4] = *(float4*)&Bs[p][tx * 8 + 4];
#pragma unroll
            for (int m = 0; m < 8; m++)
#pragma unroll
                for (int n = 0; n < 8; n++) acc[m][n] += ra[m] * rb[n];
        }
        __syncthreads();
    }

    float* Gb = g_G + (size_t)b * TDIM * TDIM;
#pragma unroll
    for (int m = 0; m < 8; m++)
#pragma unroll
        for (int n = 0; n < 8; n += 4) {
            float4 v4 = make_float4(acc[m][n], acc[m][n+1], acc[m][n+2], acc[m][n+3]);
            *(float4*)&Gb[(size_t)(o0 + ty * 8 + m) * TDIM + t0 + tx * 8 + n] = v4;
        }
}

// =============================================================================
// K4: out[b][c][o] = sum_t v[b][c][t] * G[b][o][t]
// NT gemm, M=4096 (c), N=512 (o), K=512 (t). 128x128 tile, BK=16.
// =============================================================================
__global__ void __launch_bounds__(256) k_out(const float* __restrict__ v,
                                             float* __restrict__ out)
{
    const int b  = blockIdx.z;
    const int c0 = blockIdx.y * 128;
    const int o0 = blockIdx.x * 128;

    __shared__ float As[16][132];   // [t][c]
    __shared__ float Bs[16][132];   // [t][o]

    const float* vb = v + (size_t)b * CDIM * TDIM;
    const float* Gb = g_G + (size_t)b * TDIM * TDIM;

    const int tid = threadIdx.x;
    const int tx = tid & 15, ty = tid >> 4;

    float acc[8][8];
#pragma unroll
    for (int m = 0; m < 8; m++)
#pragma unroll
        for (int n = 0; n < 8; n++) acc[m][n] = 0.f;

    for (int t0 = 0; t0 < TDIM; t0 += 16) {
#pragma unroll
        for (int i = 0; i < 2; i++) {
            int idx = tid + i * 256;
            int rl  = idx >> 2;           // 0..127
            int tq  = (idx & 3) * 4;
            float4 a = *(const float4*)&vb[(size_t)(c0 + rl) * TDIM + t0 + tq];
            As[tq + 0][rl] = a.x; As[tq + 1][rl] = a.y;
            As[tq + 2][rl] = a.z; As[tq + 3][rl] = a.w;
            float4 g4 = *(const float4*)&Gb[(size_t)(o0 + rl) * TDIM + t0 + tq];
            Bs[tq + 0][rl] = g4.x; Bs[tq + 1][rl] = g4.y;
            Bs[tq + 2][rl] = g4.z; Bs[tq + 3][rl] = g4.w;
        }
        __syncthreads();
#pragma unroll
        for (int p = 0; p < 16; p++) {
            float ra[8], rb[8];
            *(float4*)&ra[0] = *(float4*)&As[p][ty * 8];
            *(float4*)&ra[4] = *(float4*)&As[p][ty * 8 + 4];
            *(float4*)&rb[0] = *(float4*)&Bs[p][tx * 8];
            *(float4*)&rb[4] = *(float4*)&Bs[p][tx * 8 + 4];
#pragma unroll
            for (int m = 0; m < 8; m++)
#pragma unroll
                for (int n = 0; n < 8; n++) acc[m][n] += ra[m] * rb[n];
        }
        __syncthreads();
    }

#pragma unroll
    for (int m = 0; m < 8; m++)
#pragma unroll
        for (int n = 0; n < 8; n += 4) {
            float4 v4 = make_float4(acc[m][n], acc[m][n+1], acc[m][n+2], acc[m][n+3]);
            *(float4*)&out[(size_t)b * CDIM * ODIM + (size_t)(c0 + ty * 8 + m) * ODIM
                           + o0 + tx * 8 + n] = v4;
        }
}

// =============================================================================
extern "C" void kernel_launch(void* const* d_in, const int* in_sizes, int n_in,
                              void* d_out, int out_size)
{
    const float* q  = (const float*)d_in[0];
    const float* k  = (const float*)d_in[1];
    const float* v  = (const float*)d_in[2];
    const float* Wq = (const float*)d_in[3];
    const float* Wk = (const float*)d_in[4];
    const float* Wv = (const float*)d_in[5];
    const float* Wo = (const float*)d_in[6];
    float* out = (float*)d_out;
    (void)in_sizes; (void)n_in; (void)out_size;

    k_pmat  <<<dim3(4, 4, BSZ),  256>>>(q, k);
    k_umat  <<<dim3(4, NH, BSZ), 256>>>(Wk);
    k_attn_z<<<BSZ * NH,         256>>>(Wq, Wo);
    k_gmat  <<<dim3(4, 4, BSZ),  256>>>(Wv);
    k_out   <<<dim3(4, 32, BSZ), 256>>>(v, out);
}

// round 2
// speedup vs baseline: 1.4437x; 1.4437x over previous
#include <cuda_runtime.h>
#include <math.h>

// Problem constants
#define BSZ  8
#define CDIM 4096
#define TDIM 512
#define NH   8
#define HDIM 64
#define ODIM 512
#define SCALE_INV (1.0f / 22.62741699796952f)   // 1/sqrt(512)

// ---------------- scratch (static device globals; allocation-free) ----------
__device__ float g_P[BSZ * TDIM * TDIM];
__device__ float g_U[BSZ * NH * TDIM * HDIM];
__device__ float g_Z[BSZ * TDIM * TDIM];
__device__ float g_G[BSZ * TDIM * TDIM];

// ---------------- tf32 mma helpers ----------------
__device__ __forceinline__ unsigned f2tf32(float x) {
    unsigned r;
    asm("cvt.rna.tf32.f32 %0, %1;" : "=r"(r) : "f"(x));
    return r;
}

__device__ __forceinline__ void mma_tf32(float c[4], const unsigned a[4], const unsigned b[2]) {
    asm("mma.sync.aligned.m16n8k8.row.col.f32.tf32.tf32.f32 "
        "{%0,%1,%2,%3},{%4,%5,%6,%7},{%8,%9},{%0,%1,%2,%3};"
        : "+f"(c[0]), "+f"(c[1]), "+f"(c[2]), "+f"(c[3])
        : "r"(a[0]), "r"(a[1]), "r"(a[2]), "r"(a[3]),
          "r"(b[0]), "r"(b[1]));
}

// =============================================================================
// K1: P[b][t][s] = sum_c q[b][c][t] * k[b][c][s]   (TN, M=N=512, K=4096)
// Block 128x128, BK=16, 256 thr. Warps 4(M)x2(N), warp tile 32x64.
// Smem layout As[m][k] pitch 20 (transpose during staged load).
// =============================================================================
__global__ void __launch_bounds__(256) k_pmat_tc(const float* __restrict__ q,
                                                 const float* __restrict__ kk_)
{
    const int b  = blockIdx.z;
    const int t0 = blockIdx.y * 128;
    const int s0 = blockIdx.x * 128;

    __shared__ unsigned As[128 * 20];
    __shared__ unsigned Bs[128 * 20];

    const float* qb = q   + (size_t)b * CDIM * TDIM;
    const float* kb = kk_ + (size_t)b * CDIM * TDIM;

    const int tid  = threadIdx.x;
    const int lane = tid & 31;
    const int w    = tid >> 5;
    const int g    = lane >> 2;
    const int qd   = lane & 3;
    const int mb   = (w >> 1) * 32;
    const int nb   = (w & 1) * 64;

    float acc[2][8][4];
#pragma unroll
    for (int mi = 0; mi < 2; mi++)
#pragma unroll
        for (int ni = 0; ni < 8; ni++)
#pragma unroll
            for (int r = 0; r < 4; r++) acc[mi][ni][r] = 0.f;

    const int tl = tid & 127;     // t within tile
    const int ch = tid >> 7;      // 0/1

    for (int c0 = 0; c0 < CDIM; c0 += 16) {
        __syncthreads();
#pragma unroll
        for (int i = 0; i < 8; i++) {
            int c = ch + i * 2;
            As[tl * 20 + c] = f2tf32(qb[(size_t)(c0 + c) * TDIM + t0 + tl]);
            Bs[tl * 20 + c] = f2tf32(kb[(size_t)(c0 + c) * TDIM + s0 + tl]);
        }
        __syncthreads();
#pragma unroll
        for (int kk = 0; kk < 16; kk += 8) {
            unsigned af[2][4], bf[8][2];
#pragma unroll
            for (int mi = 0; mi < 2; mi++) {
                int m = mb + mi * 16 + g;
                af[mi][0] = As[m * 20 + kk + qd];
                af[mi][1] = As[(m + 8) * 20 + kk + qd];
                af[mi][2] = As[m * 20 + kk + qd + 4];
                af[mi][3] = As[(m + 8) * 20 + kk + qd + 4];
            }
#pragma unroll
            for (int ni = 0; ni < 8; ni++) {
                int n = nb + ni * 8 + g;
                bf[ni][0] = Bs[n * 20 + kk + qd];
                bf[ni][1] = Bs[n * 20 + kk + qd + 4];
            }
#pragma unroll
            for (int mi = 0; mi < 2; mi++)
#pragma unroll
                for (int ni = 0; ni < 8; ni++)
                    mma_tf32(acc[mi][ni], af[mi], bf[ni]);
        }
    }

    float* Pb = g_P + (size_t)b * TDIM * TDIM;
#pragma unroll
    for (int mi = 0; mi < 2; mi++)
#pragma unroll
        for (int ni = 0; ni < 8; ni++) {
            int row = t0 + mb + mi * 16 + g;
            int col = s0 + nb + ni * 8 + 2 * qd;
            *(float2*)&Pb[(size_t)row * TDIM + col] =
                make_float2(acc[mi][ni][0], acc[mi][ni][1]);
            *(float2*)&Pb[(size_t)(row + 8) * TDIM + col] =
                make_float2(acc[mi][ni][2], acc[mi][ni][3]);
        }
}

// =============================================================================
// K2a: U[b,h][t][e] = sum_s P[b][t][s] * Wk[h][e][s]   (NT, M=512,N=64,K=512)
// Block 128x64, warps 4(M)x2(N), warp tile 32x32.
// =============================================================================
__global__ void __launch_bounds__(256) k_umat_tc(const float* __restrict__ Wk)
{
    const int b  = blockIdx.z;
    const int h  = blockIdx.y;
    const int t0 = blockIdx.x * 128;

    __shared__ unsigned As[128 * 20];
    __shared__ unsigned Bs[64 * 20];

    const float* Pb  = g_P + (size_t)b * TDIM * TDIM;
    const float* Wkh = Wk + (size_t)h * HDIM * TDIM;

    const int tid  = threadIdx.x;
    const int lane = tid & 31;
    const int w    = tid >> 5;
    const int g    = lane >> 2;
    const int qd   = lane & 3;
    const int mb   = (w >> 1) * 32;
    const int nb   = (w & 1) * 32;

    float acc[2][4][4];
#pragma unroll
    for (int mi = 0; mi < 2; mi++)
#pragma unroll
        for (int ni = 0; ni < 4; ni++)
#pragma unroll
            for (int r = 0; r < 4; r++) acc[mi][ni][r] = 0.f;

    for (int s0 = 0; s0 < TDIM; s0 += 16) {
        __syncthreads();
#pragma unroll
        for (int i = 0; i < 2; i++) {
            int idx = tid + i * 256;
            int row = idx >> 2;
            int kq  = (idx & 3) * 4;
            float4 a = *(const float4*)&Pb[(size_t)(t0 + row) * TDIM + s0 + kq];
            As[row * 20 + kq + 0] = f2tf32(a.x);
            As[row * 20 + kq + 1] = f2tf32(a.y);
            As[row * 20 + kq + 2] = f2tf32(a.z);
            As[row * 20 + kq + 3] = f2tf32(a.w);
        }
        {
            int row = tid >> 2;           // 0..63
            int kq  = (tid & 3) * 4;
            float4 bv = *(const float4*)&Wkh[(size_t)row * TDIM + s0 + kq];
            Bs[row * 20 + kq + 0] = f2tf32(bv.x);
            Bs[row * 20 + kq + 1] = f2tf32(bv.y);
            Bs[row * 20 + kq + 2] = f2tf32(bv.z);
            Bs[row * 20 + kq + 3] = f2tf32(bv.w);
        }
        __syncthreads();
#pragma unroll
        for (int kk = 0; kk < 16; kk += 8) {
            unsigned af[2][4], bf[4][2];
#pragma unroll
            for (int mi = 0; mi < 2; mi++) {
                int m = mb + mi * 16 + g;
                af[mi][0] = As[m * 20 + kk + qd];
                af[mi][1] = As[(m + 8) * 20 + kk + qd];
                af[mi][2] = As[m * 20 + kk + qd + 4];
                af[mi][3] = As[(m + 8) * 20 + kk + qd + 4];
            }
#pragma unroll
            for (int ni = 0; ni < 4; ni++) {
                int n = nb + ni * 8 + g;
                bf[ni][0] = Bs[n * 20 + kk + qd];
                bf[ni][1] = Bs[n * 20 + kk + qd + 4];
            }
#pragma unroll
            for (int mi = 0; mi < 2; mi++)
#pragma unroll
                for (int ni = 0; ni < 4; ni++)
                    mma_tf32(acc[mi][ni], af[mi], bf[ni]);
        }
    }

    float* Ub = g_U + (size_t)(b * NH + h) * TDIM * HDIM;
#pragma unroll
    for (int mi = 0; mi < 2; mi++)
#pragma unroll
        for (int ni = 0; ni < 4; ni++) {
            int row = t0 + mb + mi * 16 + g;
            int col = nb + ni * 8 + 2 * qd;
            *(float2*)&Ub[(size_t)row * HDIM + col] =
                make_float2(acc[mi][ni][0], acc[mi][ni][1]);
            *(float2*)&Ub[(size_t)(row + 8) * HDIM + col] =
                make_float2(acc[mi][ni][2], acc[mi][ni][3]);
        }
}

// =============================================================================
// K2b: per (b,h): S = Wq_h @ U / sqrt(512); W = softmax_rows(S);
//      Z[b][o][h*64+e] = sum_d Wo[o][h*64+d] * W[d][e]
// (unchanged fp32; small)
// =============================================================================
__global__ void __launch_bounds__(256) k_attn_z(const float* __restrict__ Wq,
                                                const float* __restrict__ Wo)
{
    const int bh = blockIdx.x;
    const int b = bh >> 3, h = bh & 7;

    __shared__ float Ws[64][65];
    __shared__ float Us[32][68];
    __shared__ float Wqs[64][33];

    const float* Ub  = g_U + (size_t)bh * TDIM * HDIM;
    const float* Wqh = Wq + (size_t)h * HDIM * TDIM;

    const int tid = threadIdx.x;
    const int tx = tid & 15, ty = tid >> 4;

    float acc[4][4];
#pragma unroll
    for (int m = 0; m < 4; m++)
#pragma unroll
        for (int n = 0; n < 4; n++) acc[m][n] = 0.f;

    for (int t0 = 0; t0 < TDIM; t0 += 32) {
#pragma unroll
        for (int i = 0; i < 2; i++) {
            int idx = tid + i * 256;
            int tl  = idx >> 4;
            int eq  = (idx & 15) * 4;
            *(float4*)&Us[tl][eq] = *(const float4*)&Ub[(size_t)(t0 + tl) * HDIM + eq];
        }
#pragma unroll
        for (int i = 0; i < 2; i++) {
            int idx = tid + i * 256;
            int d   = idx >> 3;
            int tq  = (idx & 7) * 4;
            float4 a = *(const float4*)&Wqh[(size_t)d * TDIM + t0 + tq];
            Wqs[d][tq + 0] = a.x; Wqs[d][tq + 1] = a.y;
            Wqs[d][tq + 2] = a.z; Wqs[d][tq + 3] = a.w;
        }
        __syncthreads();
#pragma unroll
        for (int tl = 0; tl < 32; tl++) {
            float ra[4], rb[4];
#pragma unroll
            for (int m = 0; m < 4; m++) ra[m] = Wqs[ty * 4 + m][tl];
#pragma unroll
            for (int n = 0; n < 4; n++) rb[n] = Us[tl][tx * 4 + n];
#pragma unroll
            for (int m = 0; m < 4; m++)
#pragma unroll
                for (int n = 0; n < 4; n++) acc[m][n] += ra[m] * rb[n];
        }
        __syncthreads();
    }

#pragma unroll
    for (int m = 0; m < 4; m++)
#pragma unroll
        for (int n = 0; n < 4; n++)
            Ws[ty * 4 + m][tx * 4 + n] = acc[m][n] * SCALE_INV;
    __syncthreads();

    if (tid < 64) {
        float mx = -1e30f;
#pragma unroll 8
        for (int e = 0; e < 64; e++) mx = fmaxf(mx, Ws[tid][e]);
        float sum = 0.f;
#pragma unroll 8
        for (int e = 0; e < 64; e++) { float ex = expf(Ws[tid][e] - mx); Ws[tid][e] = ex; sum += ex; }
        float inv = 1.f / sum;
#pragma unroll 8
        for (int e = 0; e < 64; e++) Ws[tid][e] *= inv;
    }
    __syncthreads();

    float* Zb = g_Z + (size_t)b * TDIM * TDIM;
    for (int idx = tid; idx < ODIM * HDIM; idx += 256) {
        int o = idx >> 6, e = idx & 63;
        const float* wo = Wo + (size_t)o * (NH * HDIM) + h * HDIM;
        float s = 0.f;
#pragma unroll 16
        for (int d = 0; d < 64; d++) s += wo[d] * Ws[d][e];
        Zb[(size_t)o * TDIM + h * HDIM + e] = s;
    }
}

// =============================================================================
// K3: G[b][o][t] = sum_j Z[b][o][j] * Wv_flat[j][t]   (NN, M=N=K=512)
// Block 128x128. A = Z (K-major, As[m][k]); B = Wv (stored [k][n] direct).
// =============================================================================
__global__ void __launch_bounds__(256) k_gmat_tc(const float* __restrict__ Wv)
{
    const int b  = blockIdx.z;
    const int o0 = blockIdx.y * 128;
    const int t0 = blockIdx.x * 128;

    __shared__ unsigned As[128 * 20];
    __shared__ unsigned Bs[16 * 132];

    const float* Zb = g_Z + (size_t)b * TDIM * TDIM;

    const int tid  = threadIdx.x;
    const int lane = tid & 31;
    const int w    = tid >> 5;
    const int g    = lane >> 2;
    const int qd   = lane & 3;
    const int mb   = (w >> 1) * 32;
    const int nb   = (w & 1) * 64;

    float acc[2][8][4];
#pragma unroll
    for (int mi = 0; mi < 2; mi++)
#pragma unroll
        for (int ni = 0; ni < 8; ni++)
#pragma unroll
            for (int r = 0; r < 4; r++) acc[mi][ni][r] = 0.f;

    for (int j0 = 0; j0 < TDIM; j0 += 16) {
        __syncthreads();
#pragma unroll
        for (int i = 0; i < 2; i++) {
            int idx = tid + i * 256;
            // A: Z[o][j] row-major -> As[m][k]
            int row = idx >> 2;
            int kq  = (idx & 3) * 4;
            float4 a = *(const float4*)&Zb[(size_t)(o0 + row) * TDIM + j0 + kq];
            As[row * 20 + kq + 0] = f2tf32(a.x);
            As[row * 20 + kq + 1] = f2tf32(a.y);
            As[row * 20 + kq + 2] = f2tf32(a.z);
            As[row * 20 + kq + 3] = f2tf32(a.w);
            // B: Wv[j][t] k-major -> Bs[k][n]
            int r  = idx >> 5;            // 0..15
            int cc = (idx & 31) * 4;      // 0..124
            float4 bv = *(const float4*)&Wv[(size_t)(j0 + r) * TDIM + t0 + cc];
            Bs[r * 132 + cc + 0] = f2tf32(bv.x);
            Bs[r * 132 + cc + 1] = f2tf32(bv.y);
            Bs[r * 132 + cc + 2] = f2tf32(bv.z);
            Bs[r * 132 + cc + 3] = f2tf32(bv.w);
        }
        __syncthreads();
#pragma unroll
        for (int kk = 0; kk < 16; kk += 8) {
            unsigned af[2][4], bf[8][2];
#pragma unroll
            for (int mi = 0; mi < 2; mi++) {
                int m = mb + mi * 16 + g;
                af[mi][0] = As[m * 20 + kk + qd];
                af[mi][1] = As[(m + 8) * 20 + kk + qd];
                af[mi][2] = As[m * 20 + kk + qd + 4];
                af[mi][3] = As[(m + 8) * 20 + kk + qd + 4];
            }
#pragma unroll
            for (int ni = 0; ni < 8; ni++) {
                int n = nb + ni * 8 + g;
                bf[ni][0] = Bs[(kk + qd) * 132 + n];
                bf[ni][1] = Bs[(kk + qd + 4) * 132 + n];
            }
#pragma unroll
            for (int mi = 0; mi < 2; mi++)
#pragma unroll
                for (int ni = 0; ni < 8; ni++)
                    mma_tf32(acc[mi][ni], af[mi], bf[ni]);
        }
    }

    float* Gb = g_G + (size_t)b * TDIM * TDIM;
#pragma unroll
    for (int mi = 0; mi < 2; mi++)
#pragma unroll
        for (int ni = 0; ni < 8; ni++) {
            int row = o0 + mb + mi * 16 + g;
            int col = t0 + nb + ni * 8 + 2 * qd;
            *(float2*)&Gb[(size_t)row * TDIM + col] =
                make_float2(acc[mi][ni][0], acc[mi][ni][1]);
            *(float2*)&Gb[(size_t)(row + 8) * TDIM + col] =
                make_float2(acc[mi][ni][2], acc[mi][ni][3]);
        }
}

// =============================================================================
// K4: out[b][c][o] = sum_t v[b][c][t] * G[b][o][t]   (NT, M=4096,N=512,K=512)
// Block 128x128. Both operands K-major row-major -> As/Bs [row][k] pitch 20.
// =============================================================================
__global__ void __launch_bounds__(256) k_out_tc(const float* __restrict__ v,
                                                float* __restrict__ out)
{
    const int b   = blockIdx.z;
    const int c0b = blockIdx.y * 128;
    const int o0  = blockIdx.x * 128;

    __shared__ unsigned As[128 * 20];
    __shared__ unsigned Bs[128 * 20];

    const float* vb = v + (size_t)b * CDIM * TDIM;
    const float* Gb = g_G + (size_t)b * TDIM * TDIM;

    const int tid  = threadIdx.x;
    const int lane = tid & 31;
    const int w    = tid >> 5;
    const int g    = lane >> 2;
    const int qd   = lane & 3;
    const int mb   = (w >> 1) * 32;
    const int nb   = (w & 1) * 64;

    float acc[2][8][4];
#pragma unroll
    for (int mi = 0; mi < 2; mi++)
#pragma unroll
        for (int ni = 0; ni < 8; ni++)
#pragma unroll
            for (int r = 0; r < 4; r++) acc[mi][ni][r] = 0.f;

    for (int t0 = 0; t0 < TDIM; t0 += 16) {
        __syncthreads();
#pragma unroll
        for (int i = 0; i < 2; i++) {
            int idx = tid + i * 256;
            int row = idx >> 2;
            int kq  = (idx & 3) * 4;
            float4 a = *(const float4*)&vb[(size_t)(c0b + row) * TDIM + t0 + kq];
            As[row * 20 + kq + 0] = f2tf32(a.x);
            As[row * 20 + kq + 1] = f2tf32(a.y);
            As[row * 20 + kq + 2] = f2tf32(a.z);
            As[row * 20 + kq + 3] = f2tf32(a.w);
            float4 bv = *(const float4*)&Gb[(size_t)(o0 + row) * TDIM + t0 + kq];
            Bs[row * 20 + kq + 0] = f2tf32(bv.x);
            Bs[row * 20 + kq + 1] = f2tf32(bv.y);
            Bs[row * 20 + kq + 2] = f2tf32(bv.z);
            Bs[row * 20 + kq + 3] = f2tf32(bv.w);
        }
        __syncthreads();
#pragma unroll
        for (int kk = 0; kk < 16; kk += 8) {
            unsigned af[2][4], bf[8][2];
#pragma unroll
            for (int mi = 0; mi < 2; mi++) {
                int m = mb + mi * 16 + g;
                af[mi][0] = As[m * 20 + kk + qd];
                af[mi][1] = As[(m + 8) * 20 + kk + qd];
                af[mi][2] = As[m * 20 + kk + qd + 4];
                af[mi][3] = As[(m + 8) * 20 + kk + qd + 4];
            }
#pragma unroll
            for (int ni = 0; ni < 8; ni++) {
                int n = nb + ni * 8 + g;
                bf[ni][0] = Bs[n * 20 + kk + qd];
                bf[ni][1] = Bs[n * 20 + kk + qd + 4];
            }
#pragma unroll
            for (int mi = 0; mi < 2; mi++)
#pragma unroll
                for (int ni = 0; ni < 8; ni++)
                    mma_tf32(acc[mi][ni], af[mi], bf[ni]);
        }
    }

#pragma unroll
    for (int mi = 0; mi < 2; mi++)
#pragma unroll
        for (int ni = 0; ni < 8; ni++) {
            int row = c0b + mb + mi * 16 + g;
            int col = o0 + nb + ni * 8 + 2 * qd;
            *(float2*)&out[(size_t)b * CDIM * ODIM + (size_t)row * ODIM + col] =
                make_float2(acc[mi][ni][0], acc[mi][ni][1]);
            *(float2*)&out[(size_t)b * CDIM * ODIM + (size_t)(row + 8) * ODIM + col] =
                make_float2(acc[mi][ni][2], acc[mi][ni][3]);
        }
}

// =============================================================================
extern "C" void kernel_launch(void* const* d_in, const int* in_sizes, int n_in,
                              void* d_out, int out_size)
{
    const float* q  = (const float*)d_in[0];
    const float* k  = (const float*)d_in[1];
    const float* v  = (const float*)d_in[2];
    const float* Wq = (const float*)d_in[3];
    const float* Wk = (const float*)d_in[4];
    const float* Wv = (const float*)d_in[5];
    const float* Wo = (const float*)d_in[6];
    float* out = (float*)d_out;
    (void)in_sizes; (void)n_in; (void)out_size;

    k_pmat_tc<<<dim3(4, 4, BSZ),  256>>>(q, k);
    k_umat_tc<<<dim3(4, NH, BSZ), 256>>>(Wk);
    k_attn_z <<<BSZ * NH,         256>>>(Wq, Wo);
    k_gmat_tc<<<dim3(4, 4, BSZ),  256>>>(Wv);
    k_out_tc <<<dim3(4, 32, BSZ), 256>>>(v, out);
}

// round 3
// speedup vs baseline: 1.4845x; 1.0282x over previous
#include <cuda_runtime.h>
#include <math.h>

// Problem constants
#define BSZ  8
#define CDIM 4096
#define TDIM 512
#define NH   8
#define HDIM 64
#define ODIM 512
#define SCALE_INV (1.0f / 22.62741699796952f)   // 1/sqrt(512)

// ---------------- scratch (static device globals; allocation-free) ----------
__device__ float g_P[BSZ * TDIM * TDIM];
__device__ float g_U[BSZ * NH * TDIM * HDIM];
__device__ float g_Z[BSZ * TDIM * TDIM];
__device__ float g_G[BSZ * TDIM * TDIM];

// ---------------- tf32 mma helpers ----------------
__device__ __forceinline__ unsigned f2tf32(float x) {
    unsigned r;
    asm("cvt.rna.tf32.f32 %0, %1;" : "=r"(r) : "f"(x));
    return r;
}

__device__ __forceinline__ void mma_tf32(float c[4], const unsigned* a, const unsigned* b) {
    asm("mma.sync.aligned.m16n8k8.row.col.f32.tf32.tf32.f32 "
        "{%0,%1,%2,%3},{%4,%5,%6,%7},{%8,%9},{%0,%1,%2,%3};"
        : "+f"(c[0]), "+f"(c[1]), "+f"(c[2]), "+f"(c[3])
        : "r"(a[0]), "r"(a[1]), "r"(a[2]), "r"(a[3]),
          "r"(b[0]), "r"(b[1]));
}

// Fragment-packed smem slots (BK=16).
// A frag regs per lane (g=lane>>2, qd=lane&3): a0=A[g][qd] a1=A[g+8][qd]
// a2=A[g][qd+4] a3=A[g+8][qd+4].  Pack so a0..a3 are contiguous -> LDS.128.
__device__ __forceinline__ int slotA(int m, int k) {
    return ((((m >> 4) << 1) + (k >> 3)) << 7)
         + ((((m & 7) << 2) + (k & 3)) << 2)
         + ((m >> 3) & 1) + (((k >> 2) & 1) << 1);
}
// B frag regs: b0=B[n][qd] b1=B[n][qd+4] (n index g=lane>>2). Pack pairs -> LDS.64.
__device__ __forceinline__ int slotB(int n, int k) {
    return ((((n >> 3) << 1) + (k >> 3)) << 6)
         + ((((n & 7) << 2) + (k & 3)) << 1)
         + ((k >> 2) & 1);
}

// =============================================================================
// K1: P[b][t][s] = sum_c q[b][c][t] * k[b][c][s]   (TN, M=N=512, K=4096)
// 128x128 tile, BK=16, 256 thr, warps 4(M)x2(N), double-buffered, frag-packed.
// =============================================================================
__global__ void __launch_bounds__(256) k_pmat_tc(const float* __restrict__ q,
                                                 const float* __restrict__ kk_)
{
    const int b  = blockIdx.z;
    const int t0 = blockIdx.y * 128;
    const int s0 = blockIdx.x * 128;

    __shared__ unsigned Ab[2][2048];
    __shared__ unsigned Bb[2][2048];

    const float* qb = q   + (size_t)b * CDIM * TDIM;
    const float* kb = kk_ + (size_t)b * CDIM * TDIM;

    const int tid  = threadIdx.x;
    const int lane = tid & 31;
    const int w    = tid >> 5;
    const int g    = lane >> 2;
    const int qd   = lane & 3;
    const int mt0  = (w >> 1) * 2;       // mb = (w>>1)*32
    const int nt0  = (w & 1) * 8;        // nb = (w&1)*64

    const int tl = tid & 127;            // m (or n) within tile
    const int ch = tid >> 7;             // k parity 0/1; thread handles k=ch+2i

    int sA[8], sB[8];
#pragma unroll
    for (int i = 0; i < 8; i++) {
        sA[i] = slotA(tl, ch + 2 * i);
        sB[i] = slotB(tl, ch + 2 * i);
    }
    const float* gA = qb + (size_t)ch * TDIM + t0 + tl;
    const float* gB = kb + (size_t)ch * TDIM + s0 + tl;

    float acc[2][8][4];
#pragma unroll
    for (int mi = 0; mi < 2; mi++)
#pragma unroll
        for (int ni = 0; ni < 8; ni++)
#pragma unroll
            for (int r = 0; r < 4; r++) acc[mi][ni][r] = 0.f;

    float rA[8], rB[8];
    const int NC = CDIM / 16;

    // prologue: chunk 0
#pragma unroll
    for (int i = 0; i < 8; i++) {
        rA[i] = gA[(size_t)(2 * i) * TDIM];
        rB[i] = gB[(size_t)(2 * i) * TDIM];
    }
#pragma unroll
    for (int i = 0; i < 8; i++) {
        Ab[0][sA[i]] = f2tf32(rA[i]);
        Bb[0][sB[i]] = f2tf32(rB[i]);
    }
    __syncthreads();

    for (int c = 0; c < NC; c++) {
        if (c + 1 < NC) {
            const float* pA = gA + (size_t)(c + 1) * 16 * TDIM;
            const float* pB = gB + (size_t)(c + 1) * 16 * TDIM;
#pragma unroll
            for (int i = 0; i < 8; i++) {
                rA[i] = pA[(size_t)(2 * i) * TDIM];
                rB[i] = pB[(size_t)(2 * i) * TDIM];
            }
        }
        const int st = c & 1;
#pragma unroll
        for (int kbI = 0; kbI < 2; kbI++) {
            uint4 a4[2];
            uint2 b2[8];
#pragma unroll
            for (int mi = 0; mi < 2; mi++)
                a4[mi] = *(const uint4*)&Ab[st][(((mt0 + mi) << 1) + kbI) * 128 + lane * 4];
#pragma unroll
            for (int ni = 0; ni < 8; ni++)
                b2[ni] = *(const uint2*)&Bb[st][(((nt0 + ni) << 1) + kbI) * 64 + lane * 2];
#pragma unroll
            for (int mi = 0; mi < 2; mi++)
#pragma unroll
                for (int ni = 0; ni < 8; ni++)
                    mma_tf32(acc[mi][ni], (const unsigned*)&a4[mi], (const unsigned*)&b2[ni]);
        }
        if (c + 1 < NC) {
            __syncthreads();
            const int st2 = (c + 1) & 1;
#pragma unroll
            for (int i = 0; i < 8; i++) {
                Ab[st2][sA[i]] = f2tf32(rA[i]);
                Bb[st2][sB[i]] = f2tf32(rB[i]);
            }
            __syncthreads();
        }
    }

    float* Pb = g_P + (size_t)b * TDIM * TDIM;
#pragma unroll
    for (int mi = 0; mi < 2; mi++)
#pragma unroll
        for (int ni = 0; ni < 8; ni++) {
            int row = t0 + (mt0 + mi) * 16 + g;
            int col = s0 + (nt0 + ni) * 8 + 2 * qd;
            *(float2*)&Pb[(size_t)row * TDIM + col] =
                make_float2(acc[mi][ni][0], acc[mi][ni][1]);
            *(float2*)&Pb[(size_t)(row + 8) * TDIM + col] =
                make_float2(acc[mi][ni][2], acc[mi][ni][3]);
        }
}

// =============================================================================
// K2a: U[b,h][t][e] = sum_s P[b][t][s] * Wk[h][e][s]   (NT, M=512,N=64,K=512)
// 128x64 tile, BK=16, warps 4(M)x2(N) -> warp tile 32x32.
// =============================================================================
__global__ void __launch_bounds__(256) k_umat_tc(const float* __restrict__ Wk)
{
    const int b  = blockIdx.z;
    const int h  = blockIdx.y;
    const int t0 = blockIdx.x * 128;

    __shared__ unsigned Ab[2][2048];
    __shared__ unsigned Bb[2][1024];

    const float* Pb  = g_P + (size_t)b * TDIM * TDIM;
    const float* Wkh = Wk + (size_t)h * HDIM * TDIM;

    const int tid  = threadIdx.x;
    const int lane = tid & 31;
    const int w    = tid >> 5;
    const int g    = lane >> 2;
    const int qd   = lane & 3;
    const int mt0  = (w >> 1) * 2;
    const int nt0  = (w & 1) * 4;

    // A staging: 2 float4 per thread: row=idx>>2 (0..127), kq=(idx&3)*4
    const int arow0 = tid >> 2;
    const int akq   = (tid & 3) * 4;
    int sA0 = slotA(arow0, akq);
    int sA1 = slotA(arow0 + 64, akq);   // second iter: idx+256 -> row+64
    // B staging: 1 float4: row=tid>>2 (0..63), kq same
    int sB0 = slotB(arow0, akq);        // arow0<64 handled by guard below

    float acc[2][4][4];
#pragma unroll
    for (int mi = 0; mi < 2; mi++)
#pragma unroll
        for (int ni = 0; ni < 4; ni++)
#pragma unroll
            for (int r = 0; r < 4; r++) acc[mi][ni][r] = 0.f;

    float4 rA0, rA1, rB0;
    const int NC = TDIM / 16;

    rA0 = *(const float4*)&Pb[(size_t)(t0 + arow0) * TDIM + akq];
    rA1 = *(const float4*)&Pb[(size_t)(t0 + arow0 + 64) * TDIM + akq];
    if (arow0 < 64) rB0 = *(const float4*)&Wkh[(size_t)arow0 * TDIM + akq];
    {
        Ab[0][sA0 + 0] = f2tf32(rA0.x); Ab[0][sA0 + 4] = f2tf32(rA0.y);
        Ab[0][sA0 + 8] = f2tf32(rA0.z); Ab[0][sA0 + 12] = f2tf32(rA0.w);
        Ab[0][sA1 + 0] = f2tf32(rA1.x); Ab[0][sA1 + 4] = f2tf32(rA1.y);
        Ab[0][sA1 + 8] = f2tf32(rA1.z); Ab[0][sA1 + 12] = f2tf32(rA1.w);
        if (arow0 < 64) {
            Bb[0][sB0 + 0] = f2tf32(rB0.x); Bb[0][sB0 + 2] = f2tf32(rB0.y);
            Bb[0][sB0 + 4] = f2tf32(rB0.z); Bb[0][sB0 + 6] = f2tf32(rB0.w);
        }
    }
    __syncthreads();

    for (int c = 0; c < NC; c++) {
        if (c + 1 < NC) {
            int s0c = (c + 1) * 16;
            rA0 = *(const float4*)&Pb[(size_t)(t0 + arow0) * TDIM + s0c + akq];
            rA1 = *(const float4*)&Pb[(size_t)(t0 + arow0 + 64) * TDIM + s0c + akq];
            if (arow0 < 64) rB0 = *(const float4*)&Wkh[(size_t)arow0 * TDIM + s0c + akq];
        }
        const int st = c & 1;
#pragma unroll
        for (int kbI = 0; kbI < 2; kbI++) {
            uint4 a4[2];
            uint2 b2[4];
#pragma unroll
            for (int mi = 0; mi < 2; mi++)
                a4[mi] = *(const uint4*)&Ab[st][(((mt0 + mi) << 1) + kbI) * 128 + lane * 4];
#pragma unroll
            for (int ni = 0; ni < 4; ni++)
                b2[ni] = *(const uint2*)&Bb[st][(((nt0 + ni) << 1) + kbI) * 64 + lane * 2];
#pragma unroll
            for (int mi = 0; mi < 2; mi++)
#pragma unroll
                for (int ni = 0; ni < 4; ni++)
                    mma_tf32(acc[mi][ni], (const unsigned*)&a4[mi], (const unsigned*)&b2[ni]);
        }
        if (c + 1 < NC) {
            __syncthreads();
            const int st2 = (c + 1) & 1;
            Ab[st2][sA0 + 0] = f2tf32(rA0.x); Ab[st2][sA0 + 4] = f2tf32(rA0.y);
            Ab[st2][sA0 + 8] = f2tf32(rA0.z); Ab[st2][sA0 + 12] = f2tf32(rA0.w);
            Ab[st2][sA1 + 0] = f2tf32(rA1.x); Ab[st2][sA1 + 4] = f2tf32(rA1.y);
            Ab[st2][sA1 + 8] = f2tf32(rA1.z); Ab[st2][sA1 + 12] = f2tf32(rA1.w);
            if (arow0 < 64) {
                Bb[st2][sB0 + 0] = f2tf32(rB0.x); Bb[st2][sB0 + 2] = f2tf32(rB0.y);
                Bb[st2][sB0 + 4] = f2tf32(rB0.z); Bb[st2][sB0 + 6] = f2tf32(rB0.w);
            }
            __syncthreads();
        }
    }

    float* Ub = g_U + (size_t)(b * NH + h) * TDIM * HDIM;
#pragma unroll
    for (int mi = 0; mi < 2; mi++)
#pragma unroll
        for (int ni = 0; ni < 4; ni++) {
            int row = t0 + (mt0 + mi) * 16 + g;
            int col = (nt0 + ni) * 8 + 2 * qd;
            *(float2*)&Ub[(size_t)row * HDIM + col] =
                make_float2(acc[mi][ni][0], acc[mi][ni][1]);
            *(float2*)&Ub[(size_t)(row + 8) * HDIM + col] =
                make_float2(acc[mi][ni][2], acc[mi][ni][3]);
        }
}

// =============================================================================
// K2b: per (b,h): S = Wq_h @ U / sqrt(512); W = softmax_rows(S);
//      Z[b][o][h*64+e] = sum_d Wo[o][h*64+d] * W[d][e]
// =============================================================================
__global__ void __launch_bounds__(256) k_attn_z(const float* __restrict__ Wq,
                                                const float* __restrict__ Wo)
{
    const int bh = blockIdx.x;
    const int b = bh >> 3, h = bh & 7;

    __shared__ float Ws[64][65];
    __shared__ float Us[32][68];
    __shared__ float Wqs[64][33];

    const float* Ub  = g_U + (size_t)bh * TDIM * HDIM;
    const float* Wqh = Wq + (size_t)h * HDIM * TDIM;

    const int tid = threadIdx.x;
    const int tx = tid & 15, ty = tid >> 4;

    float acc[4][4];
#pragma unroll
    for (int m = 0; m < 4; m++)
#pragma unroll
        for (int n = 0; n < 4; n++) acc[m][n] = 0.f;

    for (int t0 = 0; t0 < TDIM; t0 += 32) {
#pragma unroll
        for (int i = 0; i < 2; i++) {
            int idx = tid + i * 256;
            int tl  = idx >> 4;
            int eq  = (idx & 15) * 4;
            *(float4*)&Us[tl][eq] = *(const float4*)&Ub[(size_t)(t0 + tl) * HDIM + eq];
        }
#pragma unroll
        for (int i = 0; i < 2; i++) {
            int idx = tid + i * 256;
            int d   = idx >> 3;
            int tq  = (idx & 7) * 4;
            float4 a = *(const float4*)&Wqh[(size_t)d * TDIM + t0 + tq];
            Wqs[d][tq + 0] = a.x; Wqs[d][tq + 1] = a.y;
            Wqs[d][tq + 2] = a.z; Wqs[d][tq + 3] = a.w;
        }
        __syncthreads();
#pragma unroll
        for (int tl = 0; tl < 32; tl++) {
            float ra[4], rb[4];
#pragma unroll
            for (int m = 0; m < 4; m++) ra[m] = Wqs[ty * 4 + m][tl];
#pragma unroll
            for (int n = 0; n < 4; n++) rb[n] = Us[tl][tx * 4 + n];
#pragma unroll
            for (int m = 0; m < 4; m++)
#pragma unroll
                for (int n = 0; n < 4; n++) acc[m][n] += ra[m] * rb[n];
        }
        __syncthreads();
    }

#pragma unroll
    for (int m = 0; m < 4; m++)
#pragma unroll
        for (int n = 0; n < 4; n++)
            Ws[ty * 4 + m][tx * 4 + n] = acc[m][n] * SCALE_INV;
    __syncthreads();

    if (tid < 64) {
        float mx = -1e30f;
#pragma unroll 8
        for (int e = 0; e < 64; e++) mx = fmaxf(mx, Ws[tid][e]);
        float sum = 0.f;
#pragma unroll 8
        for (int e = 0; e < 64; e++) { float ex = expf(Ws[tid][e] - mx); Ws[tid][e] = ex; sum += ex; }
        float inv = 1.f / sum;
#pragma unroll 8
        for (int e = 0; e < 64; e++) Ws[tid][e] *= inv;
    }
    __syncthreads();

    float* Zb = g_Z + (size_t)b * TDIM * TDIM;
    for (int idx = tid; idx < ODIM * HDIM; idx += 256) {
        int o = idx >> 6, e = idx & 63;
        const float* wo = Wo + (size_t)o * (NH * HDIM) + h * HDIM;
        float s = 0.f;
#pragma unroll 16
        for (int d = 0; d < 64; d++) s += wo[d] * Ws[d][e];
        Zb[(size_t)o * TDIM + h * HDIM + e] = s;
    }
}

// =============================================================================
// K3: G[b][o][t] = sum_j Z[b][o][j] * Wv_flat[j][t]   (NN, M=N=K=512)
// 128x128 tile, BK=16. A=Z K-contig; B=Wv n-contig.
// =============================================================================
__global__ void __launch_bounds__(256) k_gmat_tc(const float* __restrict__ Wv)
{
    const int b  = blockIdx.z;
    const int o0 = blockIdx.y * 128;
    const int t0 = blockIdx.x * 128;

    __shared__ unsigned Ab[2][2048];
    __shared__ unsigned Bb[2][2048];

    const float* Zb = g_Z + (size_t)b * TDIM * TDIM;

    const int tid  = threadIdx.x;
    const int lane = tid & 31;
    const int w    = tid >> 5;
    const int g    = lane >> 2;
    const int qd   = lane & 3;
    const int mt0  = (w >> 1) * 2;
    const int nt0  = (w & 1) * 8;

    // A staging: 2 float4: row=idx>>2, kq=(idx&3)*4
    const int arow0 = tid >> 2;
    const int akq   = (tid & 3) * 4;
    const int sA0 = slotA(arow0, akq);
    const int sA1 = slotA(arow0 + 64, akq);
    // B staging: 2 float4: r=idx>>5 (k), cc=(idx&31)*4 (n); slot stride 8 over n
    const int br0 = tid >> 5;          // k row 0..7 (iter adds +8)
    const int bcc = (tid & 31) * 4;    // n
    const int sB0 = slotB(bcc, br0);
    const int sB1 = slotB(bcc, br0 + 8);

    float acc[2][8][4];
#pragma unroll
    for (int mi = 0; mi < 2; mi++)
#pragma unroll
        for (int ni = 0; ni < 8; ni++)
#pragma unroll
            for (int r = 0; r < 4; r++) acc[mi][ni][r] = 0.f;

    float4 rA0, rA1, rB0, rB1;
    const int NC = TDIM / 16;

    rA0 = *(const float4*)&Zb[(size_t)(o0 + arow0) * TDIM + akq];
    rA1 = *(const float4*)&Zb[(size_t)(o0 + arow0 + 64) * TDIM + akq];
    rB0 = *(const float4*)&Wv[(size_t)br0 * TDIM + t0 + bcc];
    rB1 = *(const float4*)&Wv[(size_t)(br0 + 8) * TDIM + t0 + bcc];
    {
        Ab[0][sA0 + 0] = f2tf32(rA0.x); Ab[0][sA0 + 4] = f2tf32(rA0.y);
        Ab[0][sA0 + 8] = f2tf32(rA0.z); Ab[0][sA0 + 12] = f2tf32(rA0.w);
        Ab[0][sA1 + 0] = f2tf32(rA1.x); Ab[0][sA1 + 4] = f2tf32(rA1.y);
        Ab[0][sA1 + 8] = f2tf32(rA1.z); Ab[0][sA1 + 12] = f2tf32(rA1.w);
        Bb[0][sB0 + 0] = f2tf32(rB0.x); Bb[0][sB0 + 8] = f2tf32(rB0.y);
        Bb[0][sB0 + 16] = f2tf32(rB0.z); Bb[0][sB0 + 24] = f2tf32(rB0.w);
        Bb[0][sB1 + 0] = f2tf32(rB1.x); Bb[0][sB1 + 8] = f2tf32(rB1.y);
        Bb[0][sB1 + 16] = f2tf32(rB1.z); Bb[0][sB1 + 24] = f2tf32(rB1.w);
    }
    __syncthreads();

    for (int c = 0; c < NC; c++) {
        if (c + 1 < NC) {
            int j0 = (c + 1) * 16;
            rA0 = *(const float4*)&Zb[(size_t)(o0 + arow0) * TDIM + j0 + akq];
            rA1 = *(const float4*)&Zb[(size_t)(o0 + arow0 + 64) * TDIM + j0 + akq];
            rB0 = *(const float4*)&Wv[(size_t)(j0 + br0) * TDIM + t0 + bcc];
            rB1 = *(const float4*)&Wv[(size_t)(j0 + br0 + 8) * TDIM + t0 + bcc];
        }
        const int st = c & 1;
#pragma unroll
        for (int kbI = 0; kbI < 2; kbI++) {
            uint4 a4[2];
            uint2 b2[8];
#pragma unroll
            for (int mi = 0; mi < 2; mi++)
                a4[mi] = *(const uint4*)&Ab[st][(((mt0 + mi) << 1) + kbI) * 128 + lane * 4];
#pragma unroll
            for (int ni = 0; ni < 8; ni++)
                b2[ni] = *(const uint2*)&Bb[st][(((nt0 + ni) << 1) + kbI) * 64 + lane * 2];
#pragma unroll
            for (int mi = 0; mi < 2; mi++)
#pragma unroll
                for (int ni = 0; ni < 8; ni++)
                    mma_tf32(acc[mi][ni], (const unsigned*)&a4[mi], (const unsigned*)&b2[ni]);
        }
        if (c + 1 < NC) {
            __syncthreads();
            const int st2 = (c + 1) & 1;
            Ab[st2][sA0 + 0] = f2tf32(rA0.x); Ab[st2][sA0 + 4] = f2tf32(rA0.y);
            Ab[st2][sA0 + 8] = f2tf32(rA0.z); Ab[st2][sA0 + 12] = f2tf32(rA0.w);
            Ab[st2][sA1 + 0] = f2tf32(rA1.x); Ab[st2][sA1 + 4] = f2tf32(rA1.y);
            Ab[st2][sA1 + 8] = f2tf32(rA1.z); Ab[st2][sA1 + 12] = f2tf32(rA1.w);
            Bb[st2][sB0 + 0] = f2tf32(rB0.x); Bb[st2][sB0 + 8] = f2tf32(rB0.y);
            Bb[st2][sB0 + 16] = f2tf32(rB0.z); Bb[st2][sB0 + 24] = f2tf32(rB0.w);
            Bb[st2][sB1 + 0] = f2tf32(rB1.x); Bb[st2][sB1 + 8] = f2tf32(rB1.y);
            Bb[st2][sB1 + 16] = f2tf32(rB1.z); Bb[st2][sB1 + 24] = f2tf32(rB1.w);
            __syncthreads();
        }
    }

    float* Gb = g_G + (size_t)b * TDIM * TDIM;
#pragma unroll
    for (int mi = 0; mi < 2; mi++)
#pragma unroll
        for (int ni = 0; ni < 8; ni++) {
            int row = o0 + (mt0 + mi) * 16 + g;
            int col = t0 + (nt0 + ni) * 8 + 2 * qd;
            *(float2*)&Gb[(size_t)row * TDIM + col] =
                make_float2(acc[mi][ni][0], acc[mi][ni][1]);
            *(float2*)&Gb[(size_t)(row + 8) * TDIM + col] =
                make_float2(acc[mi][ni][2], acc[mi][ni][3]);
        }
}

// =============================================================================
// K4: out[b][c][o] = sum_t v[b][c][t] * G[b][o][t]   (NT, M=4096,N=512,K=512)
// 128x128 tile, BK=16, both operands K-contig.
// =============================================================================
__global__ void __launch_bounds__(256) k_out_tc(const float* __restrict__ v,
                                                float* __restrict__ out)
{
    const int b   = blockIdx.z;
    const int c0b = blockIdx.y * 128;
    const int o0  = blockIdx.x * 128;

    __shared__ unsigned Ab[2][2048];
    __shared__ unsigned Bb[2][2048];

    const float* vb = v + (size_t)b * CDIM * TDIM;
    const float* Gb = g_G + (size_t)b * TDIM * TDIM;

    const int tid  = threadIdx.x;
    const int lane = tid & 31;
    const int w    = tid >> 5;
    const int g    = lane >> 2;
    const int qd   = lane & 3;
    const int mt0  = (w >> 1) * 2;
    const int nt0  = (w & 1) * 8;

    const int arow0 = tid >> 2;
    const int akq   = (tid & 3) * 4;
    const int sA0 = slotA(arow0, akq);
    const int sA1 = slotA(arow0 + 64, akq);
    const int sB0 = slotB(arow0, akq);
    const int sB1 = slotB(arow0 + 64, akq);

    float acc[2][8][4];
#pragma unroll
    for (int mi = 0; mi < 2; mi++)
#pragma unroll
        for (int ni = 0; ni < 8; ni++)
#pragma unroll
            for (int r = 0; r < 4; r++) acc[mi][ni][r] = 0.f;

    float4 rA0, rA1, rB0, rB1;
    const int NC = TDIM / 16;

    rA0 = *(const float4*)&vb[(size_t)(c0b + arow0) * TDIM + akq];
    rA1 = *(const float4*)&vb[(size_t)(c0b + arow0 + 64) * TDIM + akq];
    rB0 = *(const float4*)&Gb[(size_t)(o0 + arow0) * TDIM + akq];
    rB1 = *(const float4*)&Gb[(size_t)(o0 + arow0 + 64) * TDIM + akq];
    {
        Ab[0][sA0 + 0] = f2tf32(rA0.x); Ab[0][sA0 + 4] = f2tf32(rA0.y);
        Ab[0][sA0 + 8] = f2tf32(rA0.z); Ab[0][sA0 + 12] = f2tf32(rA0.w);
        Ab[0][sA1 + 0] = f2tf32(rA1.x); Ab[0][sA1 + 4] = f2tf32(rA1.y);
        Ab[0][sA1 + 8] = f2tf32(rA1.z); Ab[0][sA1 + 12] = f2tf32(rA1.w);
        Bb[0][sB0 + 0] = f2tf32(rB0.x); Bb[0][sB0 + 2] = f2tf32(rB0.y);
        Bb[0][sB0 + 4] = f2tf32(rB0.z); Bb[0][sB0 + 6] = f2tf32(rB0.w);
        Bb[0][sB1 + 0] = f2tf32(rB1.x); Bb[0][sB1 + 2] = f2tf32(rB1.y);
        Bb[0][sB1 + 4] = f2tf32(rB1.z); Bb[0][sB1 + 6] = f2tf32(rB1.w);
    }
    __syncthreads();

    for (int c = 0; c < NC; c++) {
        if (c + 1 < NC) {
            int t0c = (c + 1) * 16;
            rA0 = *(const float4*)&vb[(size_t)(c0b + arow0) * TDIM + t0c + akq];
            rA1 = *(const float4*)&vb[(size_t)(c0b + arow0 + 64) * TDIM + t0c + akq];
            rB0 = *(const float4*)&Gb[(size_t)(o0 + arow0) * TDIM + t0c + akq];
            rB1 = *(const float4*)&Gb[(size_t)(o0 + arow0 + 64) * TDIM + t0c + akq];
        }
        const int st = c & 1;
#pragma unroll
        for (int kbI = 0; kbI < 2; kbI++) {
            uint4 a4[2];
            uint2 b2[8];
#pragma unroll
            for (int mi = 0; mi < 2; mi++)
                a4[mi] = *(const uint4*)&Ab[st][(((mt0 + mi) << 1) + kbI) * 128 + lane * 4];
#pragma unroll
            for (int ni = 0; ni < 8; ni++)
                b2[ni] = *(const uint2*)&Bb[st][(((nt0 + ni) << 1) + kbI) * 64 + lane * 2];
#pragma unroll
            for (int mi = 0; mi < 2; mi++)
#pragma unroll
                for (int ni = 0; ni < 8; ni++)
                    mma_tf32(acc[mi][ni], (const unsigned*)&a4[mi], (const unsigned*)&b2[ni]);
        }
        if (c + 1 < NC) {
            __syncthreads();
            const int st2 = (c + 1) & 1;
            Ab[st2][sA0 + 0] = f2tf32(rA0.x); Ab[st2][sA0 + 4] = f2tf32(rA0.y);
            Ab[st2][sA0 + 8] = f2tf32(rA0.z); Ab[st2][sA0 + 12] = f2tf32(rA0.w);
            Ab[st2][sA1 + 0] = f2tf32(rA1.x); Ab[st2][sA1 + 4] = f2tf32(rA1.y);
            Ab[st2][sA1 + 8] = f2tf32(rA1.z); Ab[st2][sA1 + 12] = f2tf32(rA1.w);
            Bb[st2][sB0 + 0] = f2tf32(rB0.x); Bb[st2][sB0 + 2] = f2tf32(rB0.y);
            Bb[st2][sB0 + 4] = f2tf32(rB0.z); Bb[st2][sB0 + 6] = f2tf32(rB0.w);
            Bb[st2][sB1 + 0] = f2tf32(rB1.x); Bb[st2][sB1 + 2] = f2tf32(rB1.y);
            Bb[st2][sB1 + 4] = f2tf32(rB1.z); Bb[st2][sB1 + 6] = f2tf32(rB1.w);
            __syncthreads();
        }
    }

#pragma unroll
    for (int mi = 0; mi < 2; mi++)
#pragma unroll
        for (int ni = 0; ni < 8; ni++) {
            int row = c0b + (mt0 + mi) * 16 + g;
            int col = o0 + (nt0 + ni) * 8 + 2 * qd;
            *(float2*)&out[(size_t)b * CDIM * ODIM + (size_t)row * ODIM + col] =
                make_float2(acc[mi][ni][0], acc[mi][ni][1]);
            *(float2*)&out[(size_t)b * CDIM * ODIM + (size_t)(row + 8) * ODIM + col] =
                make_float2(acc[mi][ni][2], acc[mi][ni][3]);
        }
}

// =============================================================================
extern "C" void kernel_launch(void* const* d_in, const int* in_sizes, int n_in,
                              void* d_out, int out_size)
{
    const float* q  = (const float*)d_in[0];
    const float* k  = (const float*)d_in[1];
    const float* v  = (const float*)d_in[2];
    const float* Wq = (const float*)d_in[3];
    const float* Wk = (const float*)d_in[4];
    const float* Wv = (const float*)d_in[5];
    const float* Wo = (const float*)d_in[6];
    float* out = (float*)d_out;
    (void)in_sizes; (void)n_in; (void)out_size;

    k_pmat_tc<<<dim3(4, 4, BSZ),  256>>>(q, k);
    k_umat_tc<<<dim3(4, NH, BSZ), 256>>>(Wk);
    k_attn_z <<<BSZ * NH,         256>>>(Wq, Wo);
    k_gmat_tc<<<dim3(4, 4, BSZ),  256>>>(Wv);
    k_out_tc <<<dim3(4, 32, BSZ), 256>>>(v, out);
}

// round 5
// speedup vs baseline: 2.3748x; 1.5998x over previous
#include <cuda_runtime.h>
#include <cstdint>
#include <math.h>

// Problem constants
#define BSZ  8
#define CDIM 4096
#define TDIM 512
#define NH   8
#define HDIM 64
#define ODIM 512
#define SCALE_INV (1.0f / 22.62741699796952f)   // 1/sqrt(512)

// ---------------- scratch (static device globals; allocation-free) ----------
__device__ float g_P[BSZ * TDIM * TDIM];
__device__ float g_U[BSZ * NH * TDIM * HDIM];
__device__ float g_Z[BSZ * TDIM * TDIM];
__device__ float g_G[BSZ * TDIM * TDIM];

// ---------------- helpers ----------------
__device__ __forceinline__ unsigned f2tf32(float x) {
    unsigned r;
    asm("cvt.rna.tf32.f32 %0, %1;" : "=r"(r) : "f"(x));
    return r;
}

__device__ __forceinline__ uint32_t smem_u32(const void* p) {
    uint32_t a;
    asm("{ .reg .u64 t; cvta.to.shared.u64 t, %1; cvt.u32.u64 %0, t; }" : "=r"(a) : "l"(p));
    return a;
}

__device__ __forceinline__ void cp16(uint32_t dst, const float* src) {
    asm volatile("cp.async.cg.shared.global [%0], [%1], 16;" :: "r"(dst), "l"(src));
}
#define CP_COMMIT() asm volatile("cp.async.commit_group;" ::: "memory")
#define CP_WAIT1()  asm volatile("cp.async.wait_group 1;"  ::: "memory")

__device__ __forceinline__ void mma_tf32(float* c, const unsigned* a, const unsigned* b) {
    asm("mma.sync.aligned.m16n8k8.row.col.f32.tf32.tf32.f32 "
        "{%0,%1,%2,%3},{%4,%5,%6,%7},{%8,%9},{%0,%1,%2,%3};"
        : "+f"(c[0]), "+f"(c[1]), "+f"(c[2]), "+f"(c[3])
        : "r"(a[0]), "r"(a[1]), "r"(a[2]), "r"(a[3]),
          "r"(b[0]), "r"(b[1]));
}

// =============================================================================
// Generic tf32 GEMM, 128(M) x NCOLS(N) CTA tile, BK=32, 256 threads (8 warps,
// 4Mx2N), 3-stage cp.async pipeline, raw fp32 smem + cvt at fragment load.
//
// AKC=true : A global rows are K-contiguous (A[m*lda + k])  -> smem [m][k] p36
// AKC=false: A global rows are M-contiguous (A[k*lda + m])  -> smem [k][m] p132
// Same for B with N.  (BKC=false requires NCOLS==128.)
// =============================================================================
template<int NCOLS, bool AKC, bool BKC>
__device__ __forceinline__ void gemm_cp(const float* __restrict__ A, int lda,
                                        const float* __restrict__ B, int ldb,
                                        int NC, float* __restrict__ D, int ldd)
{
    extern __shared__ float sm[];
    constexpr int ASTAGE = AKC ? 128 * 36 : 32 * 132;     // floats
    constexpr int BSTAGE = BKC ? NCOLS * 36 : 32 * 132;
    constexpr int STAGE  = ASTAGE + BSTAGE;
    constexpr int NI     = (NCOLS / 2) / 8;               // 8 or 4

    const int tid  = threadIdx.x;
    const int lane = tid & 31;
    const int w    = tid >> 5;
    const int g    = lane >> 2;
    const int qd   = lane & 3;
    const int mb   = (w >> 1) * 32;
    const int nb   = (w & 1) * (NCOLS / 2);

    auto issue = [&](int c) {
        float* stA = sm + (c % 3) * STAGE;
        if (AKC) {
#pragma unroll
            for (int it = 0; it < 4; it++) {          // 128 rows * 8 chunks
                int i   = tid + it * 256;
                int row = i >> 3, kc = (i & 7) * 4;
                cp16(smem_u32(stA + row * 36 + kc),
                     A + (size_t)row * lda + (size_t)c * 32 + kc);
            }
        } else {
#pragma unroll
            for (int it = 0; it < 4; it++) {          // 32 k-rows * 32 chunks
                int i  = tid + it * 256;
                int kr = i >> 5, mc = (i & 31) * 4;
                cp16(smem_u32(stA + kr * 132 + mc),
                     A + (size_t)(c * 32 + kr) * lda + mc);
            }
        }
        float* stB = stA + ASTAGE;
        if (BKC) {
#pragma unroll
            for (int it = 0; it < NCOLS / 32; it++) { // NCOLS rows * 8 chunks
                int i   = tid + it * 256;
                int row = i >> 3, kc = (i & 7) * 4;
                cp16(smem_u32(stB + row * 36 + kc),
                     B + (size_t)row * ldb + (size_t)c * 32 + kc);
            }
        } else {
#pragma unroll
            for (int it = 0; it < 4; it++) {
                int i  = tid + it * 256;
                int kr = i >> 5, nc = (i & 31) * 4;
                cp16(smem_u32(stB + kr * 132 + nc),
                     B + (size_t)(c * 32 + kr) * ldb + nc);
            }
        }
    };

    float acc[2][NI][4];
#pragma unroll
    for (int mi = 0; mi < 2; mi++)
#pragma unroll
        for (int ni = 0; ni < NI; ni++)
#pragma unroll
            for (int r = 0; r < 4; r++) acc[mi][ni][r] = 0.f;

    issue(0); CP_COMMIT();
    issue(1); CP_COMMIT();

    for (int c = 0; c < NC; c++) {
        CP_WAIT1();
        __syncthreads();
        const float* As = sm + (c % 3) * STAGE;
        const float* Bs = As + ASTAGE;

#pragma unroll
        for (int ks = 0; ks < 4; ks++) {
            const int kk = ks * 8;
            unsigned af[2][4];
#pragma unroll
            for (int mi = 0; mi < 2; mi++) {
                const int m = mb + mi * 16 + g;
                if (AKC) {
                    const float* p = As + m * 36 + kk + qd;
                    af[mi][0] = f2tf32(p[0]);
                    af[mi][1] = f2tf32(p[8 * 36]);
                    af[mi][2] = f2tf32(p[4]);
                    af[mi][3] = f2tf32(p[8 * 36 + 4]);
                } else {
                    const float* p = As + (kk + qd) * 132 + m;
                    af[mi][0] = f2tf32(p[0]);
                    af[mi][1] = f2tf32(p[8]);
                    af[mi][2] = f2tf32(p[4 * 132]);
                    af[mi][3] = f2tf32(p[4 * 132 + 8]);
                }
            }
            unsigned bf[NI][2];
#pragma unroll
            for (int ni = 0; ni < NI; ni++) {
                const int n = nb + ni * 8 + g;
                if (BKC) {
                    const float* p = Bs + n * 36 + kk + qd;
                    bf[ni][0] = f2tf32(p[0]);
                    bf[ni][1] = f2tf32(p[4]);
                } else {
                    const float* p = Bs + (kk + qd) * 132 + n;
                    bf[ni][0] = f2tf32(p[0]);
                    bf[ni][1] = f2tf32(p[4 * 132]);
                }
            }
#pragma unroll
            for (int mi = 0; mi < 2; mi++)
#pragma unroll
                for (int ni = 0; ni < NI; ni++)
                    mma_tf32(acc[mi][ni], af[mi], bf[ni]);
        }

        if (c + 2 < NC) issue(c + 2);
        CP_COMMIT();
        // no bottom sync needed: issue(c+2) overwrites buffer (c-1)%3, whose
        // consumers all passed this iteration's top __syncthreads().
    }

#pragma unroll
    for (int mi = 0; mi < 2; mi++)
#pragma unroll
        for (int ni = 0; ni < NI; ni++) {
            const int row = mb + mi * 16 + g;
            const int col = nb + ni * 8 + 2 * qd;
            *(float2*)&D[(size_t)row * ldd + col] =
                make_float2(acc[mi][ni][0], acc[mi][ni][1]);
            *(float2*)&D[(size_t)(row + 8) * ldd + col] =
                make_float2(acc[mi][ni][2], acc[mi][ni][3]);
        }
}

// =============================================================================
// K1: P[b][t][s] = sum_c q[b][c][t] * k[b][c][s]  (both M/N-contiguous rows)
// =============================================================================
__global__ void __launch_bounds__(256) k_pmat(const float* __restrict__ q,
                                              const float* __restrict__ kk_)
{
    const int b  = blockIdx.z;
    const int t0 = blockIdx.y * 128;
    const int s0 = blockIdx.x * 128;
    const float* Ab = q   + (size_t)b * CDIM * TDIM + t0;
    const float* Bb = kk_ + (size_t)b * CDIM * TDIM + s0;
    float* D = g_P + (size_t)b * TDIM * TDIM + (size_t)t0 * TDIM + s0;
    gemm_cp<128, false, false>(Ab, TDIM, Bb, TDIM, CDIM / 32, D, TDIM);
}

// =============================================================================
// K2a: U[b,h][t][e] = sum_s P[b][t][s] * Wk[h][e][s]  (both K-contiguous)
// =============================================================================
__global__ void __launch_bounds__(256) k_umat(const float* __restrict__ Wk)
{
    const int b  = blockIdx.z;
    const int h  = blockIdx.y;
    const int t0 = blockIdx.x * 128;
    const float* Ab = g_P + (size_t)b * TDIM * TDIM + (size_t)t0 * TDIM;
    const float* Bb = Wk + (size_t)h * HDIM * TDIM;
    float* D = g_U + (size_t)(b * NH + h) * TDIM * HDIM + (size_t)t0 * HDIM;
    gemm_cp<64, true, true>(Ab, TDIM, Bb, TDIM, TDIM / 32, D, HDIM);
}

// =============================================================================
// K2b: per (b,h): S = Wq_h @ U / sqrt(512); W = softmax_rows(S);
//      Z[b][o][h*64+e] = sum_d Wo[o][h*64+d] * W[d][e]   (fp32, small)
// =============================================================================
__global__ void __launch_bounds__(256) k_attn_z(const float* __restrict__ Wq,
                                                const float* __restrict__ Wo)
{
    const int bh = blockIdx.x;
    const int b = bh >> 3, h = bh & 7;

    __shared__ float Ws[64][65];
    __shared__ float Us[32][68];
    __shared__ float Wqs[64][33];

    const float* Ub  = g_U + (size_t)bh * TDIM * HDIM;
    const float* Wqh = Wq + (size_t)h * HDIM * TDIM;

    const int tid = threadIdx.x;
    const int tx = tid & 15, ty = tid >> 4;

    float acc[4][4];
#pragma unroll
    for (int m = 0; m < 4; m++)
#pragma unroll
        for (int n = 0; n < 4; n++) acc[m][n] = 0.f;

    for (int t0 = 0; t0 < TDIM; t0 += 32) {
#pragma unroll
        for (int i = 0; i < 2; i++) {
            int idx = tid + i * 256;
            int tl  = idx >> 4;
            int eq  = (idx & 15) * 4;
            *(float4*)&Us[tl][eq] = *(const float4*)&Ub[(size_t)(t0 + tl) * HDIM + eq];
        }
#pragma unroll
        for (int i = 0; i < 2; i++) {
            int idx = tid + i * 256;
            int d   = idx >> 3;
            int tq  = (idx & 7) * 4;
            float4 a = *(const float4*)&Wqh[(size_t)d * TDIM + t0 + tq];
            Wqs[d][tq + 0] = a.x; Wqs[d][tq + 1] = a.y;
            Wqs[d][tq + 2] = a.z; Wqs[d][tq + 3] = a.w;
        }
        __syncthreads();
#pragma unroll
        for (int tl = 0; tl < 32; tl++) {
            float ra[4], rb[4];
#pragma unroll
            for (int m = 0; m < 4; m++) ra[m] = Wqs[ty * 4 + m][tl];
#pragma unroll
            for (int n = 0; n < 4; n++) rb[n] = Us[tl][tx * 4 + n];
#pragma unroll
            for (int m = 0; m < 4; m++)
#pragma unroll
                for (int n = 0; n < 4; n++) acc[m][n] += ra[m] * rb[n];
        }
        __syncthreads();
    }

#pragma unroll
    for (int m = 0; m < 4; m++)
#pragma unroll
        for (int n = 0; n < 4; n++)
            Ws[ty * 4 + m][tx * 4 + n] = acc[m][n] * SCALE_INV;
    __syncthreads();

    if (tid < 64) {
        float mx = -1e30f;
#pragma unroll 8
        for (int e = 0; e < 64; e++) mx = fmaxf(mx, Ws[tid][e]);
        float sum = 0.f;
#pragma unroll 8
        for (int e = 0; e < 64; e++) { float ex = expf(Ws[tid][e] - mx); Ws[tid][e] = ex; sum += ex; }
        float inv = 1.f / sum;
#pragma unroll 8
        for (int e = 0; e < 64; e++) Ws[tid][e] *= inv;
    }
    __syncthreads();

    float* Zb = g_Z + (size_t)b * TDIM * TDIM;
    for (int idx = tid; idx < ODIM * HDIM; idx += 256) {
        int o = idx >> 6, e = idx & 63;
        const float* wo = Wo + (size_t)o * (NH * HDIM) + h * HDIM;
        float s = 0.f;
#pragma unroll 16
        for (int d = 0; d < 64; d++) s += wo[d] * Ws[d][e];
        Zb[(size_t)o * TDIM + h * HDIM + e] = s;
    }
}

// =============================================================================
// K3: G[b][o][t] = sum_j Z[b][o][j] * Wv_flat[j][t]  (A K-contig, B N-contig)
// =============================================================================
__global__ void __launch_bounds__(256) k_gmat(const float* __restrict__ Wv)
{
    const int b  = blockIdx.z;
    const int o0 = blockIdx.y * 128;
    const int t0 = blockIdx.x * 128;
    const float* Ab = g_Z + (size_t)b * TDIM * TDIM + (size_t)o0 * TDIM;
    const float* Bb = Wv + t0;
    float* D = g_G + (size_t)b * TDIM * TDIM + (size_t)o0 * TDIM + t0;
    gemm_cp<128, true, false>(Ab, TDIM, Bb, TDIM, TDIM / 32, D, TDIM);
}

// =============================================================================
// K4: out[b][c][o] = sum_t v[b][c][t] * G[b][o][t]  (both K-contiguous)
// =============================================================================
__global__ void __launch_bounds__(256) k_out(const float* __restrict__ v,
                                             float* __restrict__ out)
{
    const int b  = blockIdx.z;
    const int c0 = blockIdx.y * 128;
    const int o0 = blockIdx.x * 128;
    const float* Ab = v + (size_t)b * CDIM * TDIM + (size_t)c0 * TDIM;
    const float* Bb = g_G + (size_t)b * TDIM * TDIM + (size_t)o0 * TDIM;
    float* D = out + (size_t)b * CDIM * ODIM + (size_t)c0 * ODIM + o0;
    gemm_cp<128, true, true>(Ab, TDIM, Bb, TDIM, TDIM / 32, D, ODIM);
}

// =============================================================================
extern "C" void kernel_launch(void* const* d_in, const int* in_sizes, int n_in,
                              void* d_out, int out_size)
{
    const float* q  = (const float*)d_in[0];
    const float* k  = (const float*)d_in[1];
    const float* v  = (const float*)d_in[2];
    const float* Wq = (const float*)d_in[3];
    const float* Wk = (const float*)d_in[4];
    const float* Wv = (const float*)d_in[5];
    const float* Wo = (const float*)d_in[6];
    float* out = (float*)d_out;
    (void)in_sizes; (void)n_in; (void)out_size;

    // dynamic smem per kernel: 3 stages * (ASTAGE + BSTAGE) * 4 bytes
    const int SM_PMAT = 3 * (32 * 132 + 32 * 132) * 4;    // 101376
    const int SM_UMAT = 3 * (128 * 36 + 64 * 36) * 4;     //  82944
    const int SM_GMAT = 3 * (128 * 36 + 32 * 132) * 4;    // 105984
    const int SM_OUT  = 3 * (128 * 36 + 128 * 36) * 4;    // 110592

    cudaFuncSetAttribute(k_pmat, cudaFuncAttributeMaxDynamicSharedMemorySize, SM_PMAT);
    cudaFuncSetAttribute(k_umat, cudaFuncAttributeMaxDynamicSharedMemorySize, SM_UMAT);
    cudaFuncSetAttribute(k_gmat, cudaFuncAttributeMaxDynamicSharedMemorySize, SM_GMAT);
    cudaFuncSetAttribute(k_out,  cudaFuncAttributeMaxDynamicSharedMemorySize, SM_OUT);

    k_pmat<<<dim3(4, 4, BSZ),  256, SM_PMAT>>>(q, k);
    k_umat<<<dim3(4, NH, BSZ), 256, SM_UMAT>>>(Wk);
    k_attn_z<<<BSZ * NH,       256>>>(Wq, Wo);
    k_gmat<<<dim3(4, 4, BSZ),  256, SM_GMAT>>>(Wv);
    k_out <<<dim3(4, 32, BSZ), 256, SM_OUT>>>(v, out);
}

// round 6
// speedup vs baseline: 2.5016x; 1.0534x over previous
#include <cuda_runtime.h>
#include <cstdint>
#include <math.h>

// Problem constants
#define BSZ  8
#define CDIM 4096
#define TDIM 512
#define NH   8
#define HDIM 64
#define ODIM 512
#define SCALE_INV (1.0f / 22.62741699796952f)   // 1/sqrt(512)

// ---------------- scratch (static device globals; allocation-free) ----------
// g_Pd[b][t][1024]: columns 0-511 = K-half-0 partial of P, 512-1023 = half-1.
// (tf32-pre-rounded)  U = (P0+P1)@Wk^T == [P0|P1] @ [Wk|Wk]^T over K=1024.
__device__ __align__(256) float g_Pd[BSZ * TDIM * 1024];
__device__ __align__(256) float g_U [BSZ * NH * TDIM * HDIM];
__device__ __align__(256) float g_Z [BSZ * TDIM * TDIM];   // tf32-pre-rounded
__device__ __align__(256) float g_G [BSZ * TDIM * TDIM];   // tf32-pre-rounded

// ---------------- helpers ----------------
__device__ __forceinline__ unsigned f2tf32(float x) {
    unsigned r;
    asm("cvt.rna.tf32.f32 %0, %1;" : "=r"(r) : "f"(x));
    return r;
}

template<bool PRE>
__device__ __forceinline__ unsigned frag_bits(float x) {
    return PRE ? __float_as_uint(x) : f2tf32(x);
}

__device__ __forceinline__ uint32_t smem_u32(const void* p) {
    uint32_t a;
    asm("{ .reg .u64 t; cvta.to.shared.u64 t, %1; cvt.u32.u64 %0, t; }" : "=r"(a) : "l"(p));
    return a;
}

__device__ __forceinline__ void cp16(uint32_t dst, const float* src) {
    asm volatile("cp.async.cg.shared.global [%0], [%1], 16;" :: "r"(dst), "l"(src));
}
#define CP_COMMIT() asm volatile("cp.async.commit_group;" ::: "memory")
#define CP_WAIT1()  asm volatile("cp.async.wait_group 1;"  ::: "memory")

__device__ __forceinline__ void mma_tf32(float* c, const unsigned* a, const unsigned* b) {
    asm("mma.sync.aligned.m16n8k8.row.col.f32.tf32.tf32.f32 "
        "{%0,%1,%2,%3},{%4,%5,%6,%7},{%8,%9},{%0,%1,%2,%3};"
        : "+f"(c[0]), "+f"(c[1]), "+f"(c[2]), "+f"(c[3])
        : "r"(a[0]), "r"(a[1]), "r"(a[2]), "r"(a[3]),
          "r"(b[0]), "r"(b[1]));
}

// =============================================================================
// Generic tf32 GEMM, 128(M) x NCOLS(N) CTA tile, BK=32, 256 threads (8 warps,
// 4Mx2N), 3-stage cp.async pipeline, fp32 (or tf32-pre-rounded) smem.
//
// AKC : A rows K-contiguous (A[m*lda+k]) -> smem [m][k] p36, else [k][m] p132
// BKC : same for B/N. (BKC=false requires NCOLS==128.)
// APRE/BPRE: operand already tf32-rounded -> skip cvt at fragment load.
// DPRE: round output to tf32 before store (bit-exact vs consumer-side cvt).
// kmaskB: element mask applied to B's K offset (511 -> wrap at 512).
// =============================================================================
template<int NCOLS, bool AKC, bool BKC, bool APRE, bool BPRE, bool DPRE>
__device__ __forceinline__ void gemm_cp(const float* __restrict__ A, int lda,
                                        const float* __restrict__ B, int ldb,
                                        unsigned kmaskB,
                                        int NC, float* __restrict__ D, int ldd)
{
    extern __shared__ float sm[];
    constexpr int ASTAGE = AKC ? 128 * 36 : 32 * 132;     // floats
    constexpr int BSTAGE = BKC ? NCOLS * 36 : 32 * 132;
    constexpr int STAGE  = ASTAGE + BSTAGE;
    constexpr int NI     = (NCOLS / 2) / 8;               // 8 or 4

    const int tid  = threadIdx.x;
    const int lane = tid & 31;
    const int w    = tid >> 5;
    const int g    = lane >> 2;
    const int qd   = lane & 3;
    const int mb   = (w >> 1) * 32;
    const int nb   = (w & 1) * (NCOLS / 2);

    auto issue = [&](int c) {
        float* stA = sm + (c % 3) * STAGE;
        if (AKC) {
#pragma unroll
            for (int it = 0; it < 4; it++) {
                int i   = tid + it * 256;
                int row = i >> 3, kc = (i & 7) * 4;
                cp16(smem_u32(stA + row * 36 + kc),
                     A + (size_t)row * lda + (size_t)c * 32 + kc);
            }
        } else {
#pragma unroll
            for (int it = 0; it < 4; it++) {
                int i  = tid + it * 256;
                int kr = i >> 5, mc = (i & 31) * 4;
                cp16(smem_u32(stA + kr * 132 + mc),
                     A + (size_t)(c * 32 + kr) * lda + mc);
            }
        }
        float* stB = stA + ASTAGE;
        unsigned koff = ((unsigned)c * 32u) & kmaskB;
        if (BKC) {
#pragma unroll
            for (int it = 0; it < NCOLS / 32; it++) {
                int i   = tid + it * 256;
                int row = i >> 3, kc = (i & 7) * 4;
                cp16(smem_u32(stB + row * 36 + kc),
                     B + (size_t)row * ldb + koff + kc);
            }
        } else {
#pragma unroll
            for (int it = 0; it < 4; it++) {
                int i  = tid + it * 256;
                int kr = i >> 5, nc = (i & 31) * 4;
                cp16(smem_u32(stB + (size_t)kr * 132 + nc),
                     B + (size_t)(koff + kr) * ldb + nc);
            }
        }
    };

    auto loadA = [&](const float* As, int ks, unsigned af[2][4]) {
        const int kk = ks * 8;
#pragma unroll
        for (int mi = 0; mi < 2; mi++) {
            const int m = mb + mi * 16 + g;
            if (AKC) {
                const float* p = As + m * 36 + kk + qd;
                af[mi][0] = frag_bits<APRE>(p[0]);
                af[mi][1] = frag_bits<APRE>(p[8 * 36]);
                af[mi][2] = frag_bits<APRE>(p[4]);
                af[mi][3] = frag_bits<APRE>(p[8 * 36 + 4]);
            } else {
                const float* p = As + (kk + qd) * 132 + m;
                af[mi][0] = frag_bits<APRE>(p[0]);
                af[mi][1] = frag_bits<APRE>(p[8]);
                af[mi][2] = frag_bits<APRE>(p[4 * 132]);
                af[mi][3] = frag_bits<APRE>(p[4 * 132 + 8]);
            }
        }
    };

    float acc[2][NI][4];
#pragma unroll
    for (int mi = 0; mi < 2; mi++)
#pragma unroll
        for (int ni = 0; ni < NI; ni++)
#pragma unroll
            for (int r = 0; r < 4; r++) acc[mi][ni][r] = 0.f;

    issue(0); CP_COMMIT();
    issue(1); CP_COMMIT();

    for (int c = 0; c < NC; c++) {
        CP_WAIT1();
        __syncthreads();
        const float* As = sm + (c % 3) * STAGE;
        const float* Bs = As + ASTAGE;

        unsigned afd[2][2][4];
        loadA(As, 0, afd[0]);
#pragma unroll
        for (int ks = 0; ks < 4; ks++) {
            const int cur = ks & 1;
            if (ks < 3) loadA(As, ks + 1, afd[cur ^ 1]);
            const int kk = ks * 8;
            unsigned bf[NI][2];
#pragma unroll
            for (int ni = 0; ni < NI; ni++) {
                const int n = nb + ni * 8 + g;
                if (BKC) {
                    const float* p = Bs + n * 36 + kk + qd;
                    bf[ni][0] = frag_bits<BPRE>(p[0]);
                    bf[ni][1] = frag_bits<BPRE>(p[4]);
                } else {
                    const float* p = Bs + (kk + qd) * 132 + n;
                    bf[ni][0] = frag_bits<BPRE>(p[0]);
                    bf[ni][1] = frag_bits<BPRE>(p[4 * 132]);
                }
            }
#pragma unroll
            for (int mi = 0; mi < 2; mi++)
#pragma unroll
                for (int ni = 0; ni < NI; ni++)
                    mma_tf32(acc[mi][ni], afd[cur][mi], bf[ni]);
        }

        if (c + 2 < NC) issue(c + 2);
        CP_COMMIT();
        // 3 stages: issue(c+2) overwrites buffer (c-1)%3, whose consumers all
        // passed this iteration's top __syncthreads().
    }

#pragma unroll
    for (int mi = 0; mi < 2; mi++)
#pragma unroll
        for (int ni = 0; ni < NI; ni++) {
            const int row = mb + mi * 16 + g;
            const int col = nb + ni * 8 + 2 * qd;
            float v0 = acc[mi][ni][0], v1 = acc[mi][ni][1];
            float v2 = acc[mi][ni][2], v3 = acc[mi][ni][3];
            if (DPRE) {
                v0 = __uint_as_float(f2tf32(v0)); v1 = __uint_as_float(f2tf32(v1));
                v2 = __uint_as_float(f2tf32(v2)); v3 = __uint_as_float(f2tf32(v3));
            }
            *(float2*)&D[(size_t)row * ldd + col]       = make_float2(v0, v1);
            *(float2*)&D[(size_t)(row + 8) * ldd + col] = make_float2(v2, v3);
        }
}

// =============================================================================
// K1: P half: g_Pd[b][t][ph*512+s] = sum_{c in half ph} q[b][c][t] k[b][c][s]
// Split-K=2 -> 256 CTAs; output tf32-pre-rounded.
// =============================================================================
__global__ void __launch_bounds__(256, 2) k_pmat(const float* __restrict__ q,
                                                 const float* __restrict__ kk_)
{
    const int z  = blockIdx.z;
    const int b  = z >> 1;
    const int ph = z & 1;
    const int t0 = blockIdx.y * 128;
    const int s0 = blockIdx.x * 128;
    const float* Ab = q   + (size_t)b * CDIM * TDIM + (size_t)ph * (CDIM / 2) * TDIM + t0;
    const float* Bb = kk_ + (size_t)b * CDIM * TDIM + (size_t)ph * (CDIM / 2) * TDIM + s0;
    float* D = g_Pd + (size_t)b * TDIM * 1024 + (size_t)t0 * 1024 + ph * 512 + s0;
    gemm_cp<128, false, false, false, false, true>(
        Ab, TDIM, Bb, TDIM, 0x7fffffffu, (CDIM / 2) / 32, D, 1024);
}

// =============================================================================
// K2a: U[b,h][t][e] = sum_{k'=0..1023} g_Pd[b][t][k'] * WkW[e][k' mod 512]
// A pre-rounded, K=1024; B wraps at 512.
// =============================================================================
__global__ void __launch_bounds__(256, 2) k_umat(const float* __restrict__ Wk)
{
    const int b  = blockIdx.z;
    const int h  = blockIdx.y;
    const int t0 = blockIdx.x * 128;
    const float* Ab = g_Pd + (size_t)b * TDIM * 1024 + (size_t)t0 * 1024;
    const float* Bb = Wk + (size_t)h * HDIM * TDIM;
    float* D = g_U + (size_t)(b * NH + h) * TDIM * HDIM + (size_t)t0 * HDIM;
    gemm_cp<64, true, true, true, false, false>(
        Ab, 1024, Bb, TDIM, 511u, 1024 / 32, D, HDIM);
}

// =============================================================================
// K2b: per (b,h): S = Wq_h @ U / sqrt(512); W = softmax_rows(S);
//      Z[b][o][h*64+e] = sum_d Wo[o][h*64+d] * W[d][e]   (fp32, small)
// Output g_Z tf32-pre-rounded.
// =============================================================================
__global__ void __launch_bounds__(256) k_attn_z(const float* __restrict__ Wq,
                                                const float* __restrict__ Wo)
{
    const int bh = blockIdx.x;
    const int b = bh >> 3, h = bh & 7;

    __shared__ float Ws[64][65];
    __shared__ float Us[32][68];
    __shared__ float Wqs[64][33];

    const float* Ub  = g_U + (size_t)bh * TDIM * HDIM;
    const float* Wqh = Wq + (size_t)h * HDIM * TDIM;

    const int tid = threadIdx.x;
    const int tx = tid & 15, ty = tid >> 4;

    float acc[4][4];
#pragma unroll
    for (int m = 0; m < 4; m++)
#pragma unroll
        for (int n = 0; n < 4; n++) acc[m][n] = 0.f;

    for (int t0 = 0; t0 < TDIM; t0 += 32) {
#pragma unroll
        for (int i = 0; i < 2; i++) {
            int idx = tid + i * 256;
            int tl  = idx >> 4;
            int eq  = (idx & 15) * 4;
            *(float4*)&Us[tl][eq] = *(const float4*)&Ub[(size_t)(t0 + tl) * HDIM + eq];
        }
#pragma unroll
        for (int i = 0; i < 2; i++) {
            int idx = tid + i * 256;
            int d   = idx >> 3;
            int tq  = (idx & 7) * 4;
            float4 a = *(const float4*)&Wqh[(size_t)d * TDIM + t0 + tq];
            Wqs[d][tq + 0] = a.x; Wqs[d][tq + 1] = a.y;
            Wqs[d][tq + 2] = a.z; Wqs[d][tq + 3] = a.w;
        }
        __syncthreads();
#pragma unroll
        for (int tl = 0; tl < 32; tl++) {
            float ra[4], rb[4];
#pragma unroll
            for (int m = 0; m < 4; m++) ra[m] = Wqs[ty * 4 + m][tl];
#pragma unroll
            for (int n = 0; n < 4; n++) rb[n] = Us[tl][tx * 4 + n];
#pragma unroll
            for (int m = 0; m < 4; m++)
#pragma unroll
                for (int n = 0; n < 4; n++) acc[m][n] += ra[m] * rb[n];
        }
        __syncthreads();
    }

#pragma unroll
    for (int m = 0; m < 4; m++)
#pragma unroll
        for (int n = 0; n < 4; n++)
            Ws[ty * 4 + m][tx * 4 + n] = acc[m][n] * SCALE_INV;
    __syncthreads();

    if (tid < 64) {
        float mx = -1e30f;
#pragma unroll 8
        for (int e = 0; e < 64; e++) mx = fmaxf(mx, Ws[tid][e]);
        float sum = 0.f;
#pragma unroll 8
        for (int e = 0; e < 64; e++) { float ex = expf(Ws[tid][e] - mx); Ws[tid][e] = ex; sum += ex; }
        float inv = 1.f / sum;
#pragma unroll 8
        for (int e = 0; e < 64; e++) Ws[tid][e] *= inv;
    }
    __syncthreads();

    float* Zb = g_Z + (size_t)b * TDIM * TDIM;
    for (int idx = tid; idx < ODIM * HDIM; idx += 256) {
        int o = idx >> 6, e = idx & 63;
        const float* wo = Wo + (size_t)o * (NH * HDIM) + h * HDIM;
        float s = 0.f;
#pragma unroll 16
        for (int d = 0; d < 64; d++) s += wo[d] * Ws[d][e];
        Zb[(size_t)o * TDIM + h * HDIM + e] = __uint_as_float(f2tf32(s));
    }
}

// =============================================================================
// K3: G[b][o][t] = sum_j Z[b][o][j] * Wv_flat[j][t]  (A pre-rounded, B raw)
// Output g_G tf32-pre-rounded.
// =============================================================================
__global__ void __launch_bounds__(256, 2) k_gmat(const float* __restrict__ Wv)
{
    const int b  = blockIdx.z;
    const int o0 = blockIdx.y * 128;
    const int t0 = blockIdx.x * 128;
    const float* Ab = g_Z + (size_t)b * TDIM * TDIM + (size_t)o0 * TDIM;
    const float* Bb = Wv + t0;
    float* D = g_G + (size_t)b * TDIM * TDIM + (size_t)o0 * TDIM + t0;
    gemm_cp<128, true, false, true, false, true>(
        Ab, TDIM, Bb, TDIM, 0x7fffffffu, TDIM / 32, D, TDIM);
}

// =============================================================================
// K4: out[b][c][o] = sum_t v[b][c][t] * G[b][o][t]  (A raw, B pre-rounded)
// =============================================================================
__global__ void __launch_bounds__(256, 2) k_out(const float* __restrict__ v,
                                                float* __restrict__ out)
{
    const int b  = blockIdx.z;
    const int c0 = blockIdx.y * 128;
    const int o0 = blockIdx.x * 128;
    const float* Ab = v + (size_t)b * CDIM * TDIM + (size_t)c0 * TDIM;
    const float* Bb = g_G + (size_t)b * TDIM * TDIM + (size_t)o0 * TDIM;
    float* D = out + (size_t)b * CDIM * ODIM + (size_t)c0 * ODIM + o0;
    gemm_cp<128, true, true, false, true, false>(
        Ab, TDIM, Bb, TDIM, 0x7fffffffu, TDIM / 32, D, ODIM);
}

// =============================================================================
extern "C" void kernel_launch(void* const* d_in, const int* in_sizes, int n_in,
                              void* d_out, int out_size)
{
    const float* q  = (const float*)d_in[0];
    const float* k  = (const float*)d_in[1];
    const float* v  = (const float*)d_in[2];
    const float* Wq = (const float*)d_in[3];
    const float* Wk = (const float*)d_in[4];
    const float* Wv = (const float*)d_in[5];
    const float* Wo = (const float*)d_in[6];
    float* out = (float*)d_out;
    (void)in_sizes; (void)n_in; (void)out_size;

    // dynamic smem per kernel: 3 stages * (ASTAGE + BSTAGE) * 4 bytes
    const int SM_PMAT = 3 * (32 * 132 + 32 * 132) * 4;    // 101376
    const int SM_UMAT = 3 * (128 * 36 + 64 * 36) * 4;     //  82944
    const int SM_GMAT = 3 * (128 * 36 + 32 * 132) * 4;    // 105984
    const int SM_OUT  = 3 * (128 * 36 + 128 * 36) * 4;    // 110592

    cudaFuncSetAttribute(k_pmat, cudaFuncAttributeMaxDynamicSharedMemorySize, SM_PMAT);
    cudaFuncSetAttribute(k_umat, cudaFuncAttributeMaxDynamicSharedMemorySize, SM_UMAT);
    cudaFuncSetAttribute(k_gmat, cudaFuncAttributeMaxDynamicSharedMemorySize, SM_GMAT);
    cudaFuncSetAttribute(k_out,  cudaFuncAttributeMaxDynamicSharedMemorySize, SM_OUT);

    k_pmat<<<dim3(4, 4, BSZ * 2), 256, SM_PMAT>>>(q, k);
    k_umat<<<dim3(4, NH, BSZ),    256, SM_UMAT>>>(Wk);
    k_attn_z<<<BSZ * NH,          256>>>(Wq, Wo);
    k_gmat<<<dim3(4, 4, BSZ),     256, SM_GMAT>>>(Wv);
    k_out <<<dim3(4, 32, BSZ),    256, SM_OUT>>>(v, out);
}

// round 7
// speedup vs baseline: 3.5618x; 1.4238x over previous
#include <cuda_runtime.h>
#include <cstdint>
#include <math.h>

// Problem constants
#define BSZ  8
#define CDIM 4096
#define TDIM 512
#define NH   8
#define HDIM 64
#define ODIM 512
#define SCALE_INV (1.0f / 22.62741699796952f)   // 1/sqrt(512)

// ---------------- scratch (static device globals; allocation-free) ----------
// g_Pd[b][t][1024]: columns 0-511 = K-half-0 partial of P, 512-1023 = half-1.
// (tf32-pre-rounded)  U = (P0+P1)@Wk^T == [P0|P1] @ [Wk|Wk]^T over K=1024.
__device__ __align__(256) float g_Pd[BSZ * TDIM * 1024];
__device__ __align__(256) float g_U [BSZ * NH * TDIM * HDIM];
__device__ __align__(256) float g_W [BSZ * NH * HDIM * HDIM];  // W^T, tf32-pre-rounded
__device__ __align__(256) float g_Z [BSZ * TDIM * TDIM];       // tf32-pre-rounded
__device__ __align__(256) float g_G [BSZ * TDIM * TDIM];       // tf32-pre-rounded

// ---------------- helpers ----------------
__device__ __forceinline__ unsigned f2tf32(float x) {
    unsigned r;
    asm("cvt.rna.tf32.f32 %0, %1;" : "=r"(r) : "f"(x));
    return r;
}

template<bool PRE>
__device__ __forceinline__ unsigned frag_bits(float x) {
    return PRE ? __float_as_uint(x) : f2tf32(x);
}

__device__ __forceinline__ uint32_t smem_u32(const void* p) {
    uint32_t a;
    asm("{ .reg .u64 t; cvta.to.shared.u64 t, %1; cvt.u32.u64 %0, t; }" : "=r"(a) : "l"(p));
    return a;
}

__device__ __forceinline__ void cp16(uint32_t dst, const float* src) {
    asm volatile("cp.async.cg.shared.global [%0], [%1], 16;" :: "r"(dst), "l"(src));
}
#define CP_COMMIT() asm volatile("cp.async.commit_group;" ::: "memory")
#define CP_WAIT1()  asm volatile("cp.async.wait_group 1;"  ::: "memory")

__device__ __forceinline__ void mma_tf32(float* c, const unsigned* a, const unsigned* b) {
    asm("mma.sync.aligned.m16n8k8.row.col.f32.tf32.tf32.f32 "
        "{%0,%1,%2,%3},{%4,%5,%6,%7},{%8,%9},{%0,%1,%2,%3};"
        : "+f"(c[0]), "+f"(c[1]), "+f"(c[2]), "+f"(c[3])
        : "r"(a[0]), "r"(a[1]), "r"(a[2]), "r"(a[3]),
          "r"(b[0]), "r"(b[1]));
}

// =============================================================================
// Generic tf32 GEMM, 128(M) x NCOLS(N) CTA tile, BK=32, 256 threads (8 warps,
// 4Mx2N), 3-stage cp.async pipeline, fp32 (or tf32-pre-rounded) smem.
//
// AKC : A rows K-contiguous (A[m*lda+k]) -> smem [m][k] p36, else [k][m] p132
// BKC : B rows K-contiguous -> [n][k] p36, else [k][n] pitch NCOLS+4
// APRE/BPRE: operand already tf32-rounded -> skip cvt at fragment load.
// DPRE: round output to tf32 before store (bit-exact vs consumer-side cvt).
// kmaskB: element mask applied to B's K offset (511 -> wrap at 512).
// =============================================================================
template<int NCOLS, bool AKC, bool BKC, bool APRE, bool BPRE, bool DPRE>
__device__ __forceinline__ void gemm_cp(const float* __restrict__ A, int lda,
                                        const float* __restrict__ B, int ldb,
                                        unsigned kmaskB,
                                        int NC, float* __restrict__ D, int ldd)
{
    extern __shared__ float sm[];
    constexpr int BPITCH = NCOLS + 4;                     // BKC=false pitch
    constexpr int ASTAGE = AKC ? 128 * 36 : 32 * 132;     // floats
    constexpr int BSTAGE = BKC ? NCOLS * 36 : 32 * BPITCH;
    constexpr int STAGE  = ASTAGE + BSTAGE;
    constexpr int NI     = (NCOLS / 2) / 8;               // 8 or 4

    const int tid  = threadIdx.x;
    const int lane = tid & 31;
    const int w    = tid >> 5;
    const int g    = lane >> 2;
    const int qd   = lane & 3;
    const int mb   = (w >> 1) * 32;
    const int nb   = (w & 1) * (NCOLS / 2);

    auto issue = [&](int c) {
        float* stA = sm + (c % 3) * STAGE;
        if (AKC) {
#pragma unroll
            for (int it = 0; it < 4; it++) {
                int i   = tid + it * 256;
                int row = i >> 3, kc = (i & 7) * 4;
                cp16(smem_u32(stA + row * 36 + kc),
                     A + (size_t)row * lda + (size_t)c * 32 + kc);
            }
        } else {
#pragma unroll
            for (int it = 0; it < 4; it++) {
                int i  = tid + it * 256;
                int kr = i >> 5, mc = (i & 31) * 4;
                cp16(smem_u32(stA + kr * 132 + mc),
                     A + (size_t)(c * 32 + kr) * lda + mc);
            }
        }
        float* stB = stA + ASTAGE;
        unsigned koff = ((unsigned)c * 32u) & kmaskB;
        if (BKC) {
#pragma unroll
            for (int it = 0; it < NCOLS / 32; it++) {
                int i   = tid + it * 256;
                int row = i >> 3, kc = (i & 7) * 4;
                cp16(smem_u32(stB + row * 36 + kc),
                     B + (size_t)row * ldb + koff + kc);
            }
        } else {
#pragma unroll
            for (int it = 0; it < NCOLS / 32; it++) {
                int i  = tid + it * 256;
                int kr = i / (NCOLS / 4);
                int nc = (i % (NCOLS / 4)) * 4;
                cp16(smem_u32(stB + (size_t)kr * BPITCH + nc),
                     B + (size_t)(koff + kr) * ldb + nc);
            }
        }
    };

    auto loadA = [&](const float* As, int ks, unsigned af[2][4]) {
        const int kk = ks * 8;
#pragma unroll
        for (int mi = 0; mi < 2; mi++) {
            const int m = mb + mi * 16 + g;
            if (AKC) {
                const float* p = As + m * 36 + kk + qd;
                af[mi][0] = frag_bits<APRE>(p[0]);
                af[mi][1] = frag_bits<APRE>(p[8 * 36]);
                af[mi][2] = frag_bits<APRE>(p[4]);
                af[mi][3] = frag_bits<APRE>(p[8 * 36 + 4]);
            } else {
                const float* p = As + (kk + qd) * 132 + m;
                af[mi][0] = frag_bits<APRE>(p[0]);
                af[mi][1] = frag_bits<APRE>(p[8]);
                af[mi][2] = frag_bits<APRE>(p[4 * 132]);
                af[mi][3] = frag_bits<APRE>(p[4 * 132 + 8]);
            }
        }
    };

    float acc[2][NI][4];
#pragma unroll
    for (int mi = 0; mi < 2; mi++)
#pragma unroll
        for (int ni = 0; ni < NI; ni++)
#pragma unroll
            for (int r = 0; r < 4; r++) acc[mi][ni][r] = 0.f;

    issue(0); CP_COMMIT();
    issue(1); CP_COMMIT();

    for (int c = 0; c < NC; c++) {
        CP_WAIT1();
        __syncthreads();
        const float* As = sm + (c % 3) * STAGE;
        const float* Bs = As + ASTAGE;

        unsigned afd[2][2][4];
        loadA(As, 0, afd[0]);
#pragma unroll
        for (int ks = 0; ks < 4; ks++) {
            const int cur = ks & 1;
            if (ks < 3) loadA(As, ks + 1, afd[cur ^ 1]);
            const int kk = ks * 8;
            unsigned bf[NI][2];
#pragma unroll
            for (int ni = 0; ni < NI; ni++) {
                const int n = nb + ni * 8 + g;
                if (BKC) {
                    const float* p = Bs + n * 36 + kk + qd;
                    bf[ni][0] = frag_bits<BPRE>(p[0]);
                    bf[ni][1] = frag_bits<BPRE>(p[4]);
                } else {
                    const float* p = Bs + (kk + qd) * BPITCH + n;
                    bf[ni][0] = frag_bits<BPRE>(p[0]);
                    bf[ni][1] = frag_bits<BPRE>(p[4 * BPITCH]);
                }
            }
#pragma unroll
            for (int mi = 0; mi < 2; mi++)
#pragma unroll
                for (int ni = 0; ni < NI; ni++)
                    mma_tf32(acc[mi][ni], afd[cur][mi], bf[ni]);
        }

        if (c + 2 < NC) issue(c + 2);
        CP_COMMIT();
        // 3 stages: issue(c+2) overwrites buffer (c-1)%3, whose consumers all
        // passed this iteration's top __syncthreads().
    }

#pragma unroll
    for (int mi = 0; mi < 2; mi++)
#pragma unroll
        for (int ni = 0; ni < NI; ni++) {
            const int row = mb + mi * 16 + g;
            const int col = nb + ni * 8 + 2 * qd;
            float v0 = acc[mi][ni][0], v1 = acc[mi][ni][1];
            float v2 = acc[mi][ni][2], v3 = acc[mi][ni][3];
            if (DPRE) {
                v0 = __uint_as_float(f2tf32(v0)); v1 = __uint_as_float(f2tf32(v1));
                v2 = __uint_as_float(f2tf32(v2)); v3 = __uint_as_float(f2tf32(v3));
            }
            *(float2*)&D[(size_t)row * ldd + col]       = make_float2(v0, v1);
            *(float2*)&D[(size_t)(row + 8) * ldd + col] = make_float2(v2, v3);
        }
}

// =============================================================================
// K1: P half: g_Pd[b][t][ph*512+s] = sum_{c in half ph} q[b][c][t] k[b][c][s]
// Split-K=2 -> 256 CTAs; output tf32-pre-rounded.
// =============================================================================
__global__ void __launch_bounds__(256, 2) k_pmat(const float* __restrict__ q,
                                                 const float* __restrict__ kk_)
{
    const int z  = blockIdx.z;
    const int b  = z >> 1;
    const int ph = z & 1;
    const int t0 = blockIdx.y * 128;
    const int s0 = blockIdx.x * 128;
    const float* Ab = q   + (size_t)b * CDIM * TDIM + (size_t)ph * (CDIM / 2) * TDIM + t0;
    const float* Bb = kk_ + (size_t)b * CDIM * TDIM + (size_t)ph * (CDIM / 2) * TDIM + s0;
    float* D = g_Pd + (size_t)b * TDIM * 1024 + (size_t)t0 * 1024 + ph * 512 + s0;
    gemm_cp<128, false, false, false, false, true>(
        Ab, TDIM, Bb, TDIM, 0x7fffffffu, (CDIM / 2) / 32, D, 1024);
}

// =============================================================================
// K2a: U[b,h][t][e] = sum_{k'=0..1023} g_Pd[b][t][k'] * Wk[h][e][k' mod 512]
// =============================================================================
__global__ void __launch_bounds__(256, 2) k_umat(const float* __restrict__ Wk)
{
    const int b  = blockIdx.z;
    const int h  = blockIdx.y;
    const int t0 = blockIdx.x * 128;
    const float* Ab = g_Pd + (size_t)b * TDIM * 1024 + (size_t)t0 * 1024;
    const float* Bb = Wk + (size_t)h * HDIM * TDIM;
    float* D = g_U + (size_t)(b * NH + h) * TDIM * HDIM + (size_t)t0 * HDIM;
    gemm_cp<64, true, true, true, false, false>(
        Ab, 1024, Bb, TDIM, 511u, 1024 / 32, D, HDIM);
}

// =============================================================================
// K2b: per (b,h): S = Wq_h @ U / sqrt(512); W = softmax_rows(S);
// store W^T (tf32-pre-rounded) -> g_W[bh][e][d]
// =============================================================================
__global__ void __launch_bounds__(256) k_attn(const float* __restrict__ Wq)
{
    const int bh = blockIdx.x;
    const int h = bh & 7;

    __shared__ float Ws[64][65];
    __shared__ float Us[32][68];
    __shared__ float Wqs[64][33];

    const float* Ub  = g_U + (size_t)bh * TDIM * HDIM;
    const float* Wqh = Wq + (size_t)h * HDIM * TDIM;

    const int tid = threadIdx.x;
    const int tx = tid & 15, ty = tid >> 4;

    float acc[4][4];
#pragma unroll
    for (int m = 0; m < 4; m++)
#pragma unroll
        for (int n = 0; n < 4; n++) acc[m][n] = 0.f;

    for (int t0 = 0; t0 < TDIM; t0 += 32) {
#pragma unroll
        for (int i = 0; i < 2; i++) {
            int idx = tid + i * 256;
            int tl  = idx >> 4;
            int eq  = (idx & 15) * 4;
            *(float4*)&Us[tl][eq] = *(const float4*)&Ub[(size_t)(t0 + tl) * HDIM + eq];
        }
#pragma unroll
        for (int i = 0; i < 2; i++) {
            int idx = tid + i * 256;
            int d   = idx >> 3;
            int tq  = (idx & 7) * 4;
            float4 a = *(const float4*)&Wqh[(size_t)d * TDIM + t0 + tq];
            Wqs[d][tq + 0] = a.x; Wqs[d][tq + 1] = a.y;
            Wqs[d][tq + 2] = a.z; Wqs[d][tq + 3] = a.w;
        }
        __syncthreads();
#pragma unroll
        for (int tl = 0; tl < 32; tl++) {
            float ra[4], rb[4];
#pragma unroll
            for (int m = 0; m < 4; m++) ra[m] = Wqs[ty * 4 + m][tl];
#pragma unroll
            for (int n = 0; n < 4; n++) rb[n] = Us[tl][tx * 4 + n];
#pragma unroll
            for (int m = 0; m < 4; m++)
#pragma unroll
                for (int n = 0; n < 4; n++) acc[m][n] += ra[m] * rb[n];
        }
        __syncthreads();
    }

#pragma unroll
    for (int m = 0; m < 4; m++)
#pragma unroll
        for (int n = 0; n < 4; n++)
            Ws[ty * 4 + m][tx * 4 + n] = acc[m][n] * SCALE_INV;
    __syncthreads();

    if (tid < 64) {
        float mx = -1e30f;
#pragma unroll 8
        for (int e = 0; e < 64; e++) mx = fmaxf(mx, Ws[tid][e]);
        float sum = 0.f;
#pragma unroll 8
        for (int e = 0; e < 64; e++) { float ex = expf(Ws[tid][e] - mx); Ws[tid][e] = ex; sum += ex; }
        float inv = 1.f / sum;
#pragma unroll 8
        for (int e = 0; e < 64; e++) Ws[tid][e] *= inv;
    }
    __syncthreads();

    // store W^T: g_W[bh][e][d] = W[d][e], tf32-pre-rounded
    float* Wt = g_W + (size_t)bh * HDIM * HDIM;
    for (int idx = tid; idx < HDIM * HDIM; idx += 256) {
        int e = idx >> 6, d = idx & 63;
        Wt[(size_t)e * HDIM + d] = __uint_as_float(f2tf32(Ws[d][e]));
    }
}

// =============================================================================
// K2c: Z[b][o][h*64+e] = sum_d Wo[o][h*64+d] * W_h[d][e]
// Tensor-core GEMM, M=512(o) x N=64(e) x K=64(d), grid (4 o-chunks x 64 bh).
// A = Wo rows (K-contig, raw), B = W^T rows (K-contig, pre-rounded).
// =============================================================================
__global__ void __launch_bounds__(256, 2) k_zmat(const float* __restrict__ Wo)
{
    const int bh = blockIdx.y;
    const int b = bh >> 3, h = bh & 7;
    const int o0 = blockIdx.x * 128;
    const float* Ab = Wo + (size_t)o0 * (NH * HDIM) + h * HDIM;
    const float* Bb = g_W + (size_t)bh * HDIM * HDIM;
    float* D = g_Z + (size_t)b * TDIM * TDIM + (size_t)o0 * TDIM + h * HDIM;
    gemm_cp<64, true, true, false, true, true>(
        Ab, NH * HDIM, Bb, HDIM, 0x7fffffffu, HDIM / 32, D, TDIM);
}

// =============================================================================
// K3: G[b][o][t] = sum_j Z[b][o][j] * Wv_flat[j][t]  (A pre-rounded, B raw)
// 128x64 tiles -> grid 256 CTAs.  Output g_G tf32-pre-rounded.
// =============================================================================
__global__ void __launch_bounds__(256, 2) k_gmat(const float* __restrict__ Wv)
{
    const int b  = blockIdx.z;
    const int o0 = blockIdx.y * 128;
    const int t0 = blockIdx.x * 64;
    const float* Ab = g_Z + (size_t)b * TDIM * TDIM + (size_t)o0 * TDIM;
    const float* Bb = Wv + t0;
    float* D = g_G + (size_t)b * TDIM * TDIM + (size_t)o0 * TDIM + t0;
    gemm_cp<64, true, false, true, false, true>(
        Ab, TDIM, Bb, TDIM, 0x7fffffffu, TDIM / 32, D, TDIM);
}

// =============================================================================
// K4: out[b][c][o] = sum_t v[b][c][t] * G[b][o][t]  (A raw, B pre-rounded)
// =============================================================================
__global__ void __launch_bounds__(256, 2) k_out(const float* __restrict__ v,
                                                float* __restrict__ out)
{
    const int b  = blockIdx.z;
    const int c0 = blockIdx.y * 128;
    const int o0 = blockIdx.x * 128;
    const float* Ab = v + (size_t)b * CDIM * TDIM + (size_t)c0 * TDIM;
    const float* Bb = g_G + (size_t)b * TDIM * TDIM + (size_t)o0 * TDIM;
    float* D = out + (size_t)b * CDIM * ODIM + (size_t)c0 * ODIM + o0;
    gemm_cp<128, true, true, false, true, false>(
        Ab, TDIM, Bb, TDIM, 0x7fffffffu, TDIM / 32, D, ODIM);
}

// =============================================================================
extern "C" void kernel_launch(void* const* d_in, const int* in_sizes, int n_in,
                              void* d_out, int out_size)
{
    const float* q  = (const float*)d_in[0];
    const float* k  = (const float*)d_in[1];
    const float* v  = (const float*)d_in[2];
    const float* Wq = (const float*)d_in[3];
    const float* Wk = (const float*)d_in[4];
    const float* Wv = (const float*)d_in[5];
    const float* Wo = (const float*)d_in[6];
    float* out = (float*)d_out;
    (void)in_sizes; (void)n_in; (void)out_size;

    // dynamic smem per kernel: 3 stages * (ASTAGE + BSTAGE) * 4 bytes
    const int SM_PMAT = 3 * (32 * 132 + 32 * 132) * 4;    // 101376
    const int SM_UMAT = 3 * (128 * 36 + 64 * 36) * 4;     //  82944
    const int SM_ZMAT = 3 * (128 * 36 + 64 * 36) * 4;     //  82944
    const int SM_GMAT = 3 * (128 * 36 + 32 * 68) * 4;     //  81408
    const int SM_OUT  = 3 * (128 * 36 + 128 * 36) * 4;    // 110592

    cudaFuncSetAttribute(k_pmat, cudaFuncAttributeMaxDynamicSharedMemorySize, SM_PMAT);
    cudaFuncSetAttribute(k_umat, cudaFuncAttributeMaxDynamicSharedMemorySize, SM_UMAT);
    cudaFuncSetAttribute(k_zmat, cudaFuncAttributeMaxDynamicSharedMemorySize, SM_ZMAT);
    cudaFuncSetAttribute(k_gmat, cudaFuncAttributeMaxDynamicSharedMemorySize, SM_GMAT);
    cudaFuncSetAttribute(k_out,  cudaFuncAttributeMaxDynamicSharedMemorySize, SM_OUT);

    k_pmat<<<dim3(4, 4, BSZ * 2), 256, SM_PMAT>>>(q, k);
    k_umat<<<dim3(4, NH, BSZ),    256, SM_UMAT>>>(Wk);
    k_attn<<<BSZ * NH,            256>>>(Wq);
    k_zmat<<<dim3(4, BSZ * NH),   256, SM_ZMAT>>>(Wo);
    k_gmat<<<dim3(8, 4, BSZ),     256, SM_GMAT>>>(Wv);
    k_out <<<dim3(4, 32, BSZ),    256, SM_OUT>>>(v, out);
}